// round 1
// baseline (speedup 1.0000x reference)
#include <cuda_runtime.h>
#include <math.h>

// Problem constants
#define BB 2
#define SS 2048
#define DD 2048
#define HH 16
#define HD 128
#define MROWS (BB*SS)   // 4096

// Scratch (allocation-free rule: __device__ globals)
__device__ float g_q[(size_t)MROWS*DD];
__device__ float g_k[(size_t)MROWS*DD];
__device__ float g_v[(size_t)MROWS*DD];
__device__ float g_att[(size_t)MROWS*DD];

// ---------------------------------------------------------------------------
// GEMM: C[M,N] = A[M,K] * B[N,K]^T   (both row-major, K contiguous)
// 128x128 block tile, K-tile 16, 256 threads, 8x8 per thread.
// ---------------------------------------------------------------------------
__global__ __launch_bounds__(256, 2)
void gemm_nt(const float* __restrict__ A, const float* __restrict__ B,
             float* __restrict__ C, int M, int N, int K) {
    __shared__ float As[16][132];   // [k][m], padded stride for conflict-free access
    __shared__ float Bs[16][132];   // [k][n]

    const int tid = threadIdx.x;
    const int tx = tid & 15;
    const int ty = tid >> 4;
    const int m0 = blockIdx.y * 128;
    const int n0 = blockIdx.x * 128;

    float acc[8][8];
#pragma unroll
    for (int i = 0; i < 8; i++)
#pragma unroll
        for (int j = 0; j < 8; j++) acc[i][j] = 0.f;

    for (int k0 = 0; k0 < K; k0 += 16) {
        // Load 128x16 tiles of A and B, transposing to k-major in smem.
#pragma unroll
        for (int l = 0; l < 2; l++) {
            int f  = tid + l * 256;          // 0..511 -> float4 index
            int r  = f >> 2;                 // row within tile 0..127
            int kk = (f & 3) << 2;           // k offset 0,4,8,12
            float4 av = *(const float4*)&A[(size_t)(m0 + r) * K + k0 + kk];
            As[kk + 0][r] = av.x; As[kk + 1][r] = av.y;
            As[kk + 2][r] = av.z; As[kk + 3][r] = av.w;
            float4 bv = *(const float4*)&B[(size_t)(n0 + r) * K + k0 + kk];
            Bs[kk + 0][r] = bv.x; Bs[kk + 1][r] = bv.y;
            Bs[kk + 2][r] = bv.z; Bs[kk + 3][r] = bv.w;
        }
        __syncthreads();

#pragma unroll
        for (int kk = 0; kk < 16; kk++) {
            float a[8], b[8];
            *(float4*)&a[0] = *(const float4*)&As[kk][ty * 8];
            *(float4*)&a[4] = *(const float4*)&As[kk][ty * 8 + 4];
            *(float4*)&b[0] = *(const float4*)&Bs[kk][tx * 8];
            *(float4*)&b[4] = *(const float4*)&Bs[kk][tx * 8 + 4];
#pragma unroll
            for (int i = 0; i < 8; i++)
#pragma unroll
                for (int j = 0; j < 8; j++)
                    acc[i][j] += a[i] * b[j];
        }
        __syncthreads();
    }

#pragma unroll
    for (int i = 0; i < 8; i++) {
        float4* cp = (float4*)&C[(size_t)(m0 + ty * 8 + i) * N + n0 + tx * 8];
        cp[0] = make_float4(acc[i][0], acc[i][1], acc[i][2], acc[i][3]);
        cp[1] = make_float4(acc[i][4], acc[i][5], acc[i][6], acc[i][7]);
    }
}

// ---------------------------------------------------------------------------
// Flash attention, fp32. One block per (q-tile of 64 rows, b*h pair).
// 256 threads as 16x16. Online softmax. Smem row stride 132 (bank-safe).
// ---------------------------------------------------------------------------
#define QROW 132
#define ATTN_SMEM_FLOATS (3 * 64 * QROW + 64 * 64 + 3 * 64)
#define ATTN_SMEM_BYTES  (ATTN_SMEM_FLOATS * 4)

__global__ __launch_bounds__(256, 1)
void attn_kernel(const float* __restrict__ Q, const float* __restrict__ K,
                 const float* __restrict__ V, float* __restrict__ O) {
    extern __shared__ float sm[];
    float* Qs  = sm;                   // 64 x 132
    float* Ks  = Qs + 64 * QROW;       // 64 x 132
    float* Vs  = Ks + 64 * QROW;       // 64 x 132
    float* Ps  = Vs + 64 * QROW;       // 64 x 64
    float* m_s = Ps + 64 * 64;         // 64
    float* l_s = m_s + 64;             // 64
    float* sc_s = l_s + 64;            // 64

    const int tid = threadIdx.x;
    const int tx = tid & 15;
    const int ty = tid >> 4;
    const int qt = blockIdx.x;          // 0..31 q tile
    const int bh = blockIdx.y;          // 0..31
    const int b  = bh >> 4;
    const int h  = bh & 15;

    const size_t qbase = ((size_t)(b * SS + qt * 64)) * DD + (size_t)h * HD;
    const size_t kbase = ((size_t)(b * SS)) * DD + (size_t)h * HD;
    const float scale = 0.08838834764831845f;   // 1/sqrt(128)

    // Load Q tile (64x128), scaled.
#pragma unroll
    for (int l = 0; l < 8; l++) {
        int f = tid + l * 256;            // 0..2047 float4 index
        int r = f >> 5;                   // 0..63
        int c4 = (f & 31) << 2;           // 0..124
        float4 v = *(const float4*)&Q[qbase + (size_t)r * DD + c4];
        v.x *= scale; v.y *= scale; v.z *= scale; v.w *= scale;
        *(float4*)&Qs[r * QROW + c4] = v;
    }
    if (tid < 64) { m_s[tid] = -1e30f; l_s[tid] = 0.f; }

    float o[4][8];
#pragma unroll
    for (int i = 0; i < 4; i++)
#pragma unroll
        for (int j = 0; j < 8; j++) o[i][j] = 0.f;

    for (int kt = 0; kt < SS / 64; kt++) {
        const size_t ktile = kbase + (size_t)kt * 64 * DD;
#pragma unroll
        for (int l = 0; l < 8; l++) {
            int f = tid + l * 256;
            int r = f >> 5;
            int c4 = (f & 31) << 2;
            *(float4*)&Ks[r * QROW + c4] = *(const float4*)&K[ktile + (size_t)r * DD + c4];
            *(float4*)&Vs[r * QROW + c4] = *(const float4*)&V[ktile + (size_t)r * DD + c4];
        }
        __syncthreads();

        // S = Qs * Ks^T  (thread computes rows ty*4+i, cols tx*4+j)
        float s[4][4];
#pragma unroll
        for (int i = 0; i < 4; i++)
#pragma unroll
            for (int j = 0; j < 4; j++) s[i][j] = 0.f;

#pragma unroll 8
        for (int k = 0; k < 128; k += 4) {
            float4 qv[4], kv[4];
#pragma unroll
            for (int i = 0; i < 4; i++)
                qv[i] = *(const float4*)&Qs[(ty * 4 + i) * QROW + k];
#pragma unroll
            for (int j = 0; j < 4; j++)
                kv[j] = *(const float4*)&Ks[(tx * 4 + j) * QROW + k];
#pragma unroll
            for (int i = 0; i < 4; i++)
#pragma unroll
                for (int j = 0; j < 4; j++) {
                    s[i][j] += qv[i].x * kv[j].x;
                    s[i][j] += qv[i].y * kv[j].y;
                    s[i][j] += qv[i].z * kv[j].z;
                    s[i][j] += qv[i].w * kv[j].w;
                }
        }

        // Online softmax per row (16 tx lanes per row, shfl width 16)
#pragma unroll
        for (int i = 0; i < 4; i++) {
            const int r = ty * 4 + i;
            float mx = fmaxf(fmaxf(s[i][0], s[i][1]), fmaxf(s[i][2], s[i][3]));
            mx = fmaxf(mx, __shfl_xor_sync(0xffffffffu, mx, 1, 16));
            mx = fmaxf(mx, __shfl_xor_sync(0xffffffffu, mx, 2, 16));
            mx = fmaxf(mx, __shfl_xor_sync(0xffffffffu, mx, 4, 16));
            mx = fmaxf(mx, __shfl_xor_sync(0xffffffffu, mx, 8, 16));
            float m_old = m_s[r];                     // read before tx==0 writes (same warp ordering)
            float m_new = fmaxf(m_old, mx);
            float sum = 0.f;
#pragma unroll
            for (int j = 0; j < 4; j++) {
                s[i][j] = __expf(s[i][j] - m_new);
                sum += s[i][j];
            }
            sum += __shfl_xor_sync(0xffffffffu, sum, 1, 16);
            sum += __shfl_xor_sync(0xffffffffu, sum, 2, 16);
            sum += __shfl_xor_sync(0xffffffffu, sum, 4, 16);
            sum += __shfl_xor_sync(0xffffffffu, sum, 8, 16);
            if (tx == 0) {
                float sc = __expf(m_old - m_new);
                m_s[r] = m_new;
                sc_s[r] = sc;
                l_s[r] = l_s[r] * sc + sum;
            }
            *(float4*)&Ps[r * 64 + tx * 4] = make_float4(s[i][0], s[i][1], s[i][2], s[i][3]);
        }
        __syncthreads();

        // O = O*scale + P * V. Thread owns rows ty*4+i; cols tx*4+{0..3} and 64+tx*4+{0..3}.
#pragma unroll
        for (int i = 0; i < 4; i++) {
            float sc = sc_s[ty * 4 + i];
#pragma unroll
            for (int j = 0; j < 8; j++) o[i][j] *= sc;
        }
#pragma unroll 4
        for (int c = 0; c < 64; c++) {
            float4 v0 = *(const float4*)&Vs[c * QROW + tx * 4];
            float4 v1 = *(const float4*)&Vs[c * QROW + 64 + tx * 4];
#pragma unroll
            for (int i = 0; i < 4; i++) {
                float pv = Ps[(ty * 4 + i) * 64 + c];
                o[i][0] += pv * v0.x; o[i][1] += pv * v0.y;
                o[i][2] += pv * v0.z; o[i][3] += pv * v0.w;
                o[i][4] += pv * v1.x; o[i][5] += pv * v1.y;
                o[i][6] += pv * v1.z; o[i][7] += pv * v1.w;
            }
        }
        __syncthreads();
    }

    // Normalize and write out (same [B*S, D] layout as inputs)
#pragma unroll
    for (int i = 0; i < 4; i++) {
        const int r = ty * 4 + i;
        float inv = 1.0f / l_s[r];
        size_t orow = qbase + (size_t)r * DD;
        *(float4*)&O[orow + tx * 4] =
            make_float4(o[i][0] * inv, o[i][1] * inv, o[i][2] * inv, o[i][3] * inv);
        *(float4*)&O[orow + 64 + tx * 4] =
            make_float4(o[i][4] * inv, o[i][5] * inv, o[i][6] * inv, o[i][7] * inv);
    }
}

// ---------------------------------------------------------------------------
extern "C" void kernel_launch(void* const* d_in, const int* in_sizes, int n_in,
                              void* d_out, int out_size) {
    const float* x  = (const float*)d_in[0];
    const float* wq = (const float*)d_in[1];
    const float* wk = (const float*)d_in[2];
    const float* wv = (const float*)d_in[3];
    const float* wo = (const float*)d_in[4];
    float* out = (float*)d_out;

    float *q, *k, *v, *att;
    cudaGetSymbolAddress((void**)&q,   g_q);
    cudaGetSymbolAddress((void**)&k,   g_k);
    cudaGetSymbolAddress((void**)&v,   g_v);
    cudaGetSymbolAddress((void**)&att, g_att);

    cudaFuncSetAttribute(attn_kernel, cudaFuncAttributeMaxDynamicSharedMemorySize,
                         ATTN_SMEM_BYTES);

    dim3 ggrid(DD / 128, MROWS / 128);   // (16, 32)
    gemm_nt<<<ggrid, 256>>>(x, wq, q, MROWS, DD, DD);
    gemm_nt<<<ggrid, 256>>>(x, wk, k, MROWS, DD, DD);
    gemm_nt<<<ggrid, 256>>>(x, wv, v, MROWS, DD, DD);

    attn_kernel<<<dim3(32, 32), 256, ATTN_SMEM_BYTES>>>(q, k, v, att);

    gemm_nt<<<ggrid, 256>>>(att, wo, out, MROWS, DD, DD);
}

// round 4
// speedup vs baseline: 1.3676x; 1.3676x over previous
#include <cuda_runtime.h>
#include <cuda_bf16.h>
#include <math.h>
#include <stdint.h>

// Problem constants
#define BB 2
#define SS 2048
#define DD 2048
#define HH 16
#define HD 128
#define MROWS (BB*SS)   // 4096
#define GK DD           // 2048

// ---------------------------------------------------------------------------
// Scratch (allocation-free rule: __device__ globals)
// ---------------------------------------------------------------------------
__device__ float g_q[(size_t)MROWS*DD];
__device__ float g_k[(size_t)MROWS*DD];
__device__ float g_v[(size_t)MROWS*DD];
__device__ float g_att[(size_t)MROWS*DD];

__device__ __nv_bfloat16 g_xh[(size_t)MROWS*DD];
__device__ __nv_bfloat16 g_xl[(size_t)MROWS*DD];
__device__ __nv_bfloat16 g_ah[(size_t)MROWS*DD];
__device__ __nv_bfloat16 g_al[(size_t)MROWS*DD];
__device__ __nv_bfloat16 g_wh[(size_t)4*DD*DD];
__device__ __nv_bfloat16 g_wl[(size_t)4*DD*DD];

// ---------------------------------------------------------------------------
// PTX helpers (sm_100 BASELINE only: no tcgen05/TMEM)
// ---------------------------------------------------------------------------
__device__ __forceinline__ uint32_t smem_u32(const void* p) {
    uint32_t a;
    asm("{ .reg .u64 t; cvta.to.shared.u64 t, %1; cvt.u32.u64 %0, t; }" : "=r"(a) : "l"(p));
    return a;
}
__device__ __forceinline__ void cpa16(uint32_t dst, const void* src) {
    asm volatile("cp.async.cg.shared.global [%0], [%1], 16;\n" :: "r"(dst), "l"(src));
}
__device__ __forceinline__ void cp_commit() {
    asm volatile("cp.async.commit_group;" ::: "memory");
}
template <int N>
__device__ __forceinline__ void cp_wait() {
    asm volatile("cp.async.wait_group %0;" :: "n"(N) : "memory");
}
__device__ __forceinline__ void ldsm_x4(uint32_t& r0, uint32_t& r1, uint32_t& r2, uint32_t& r3,
                                        uint32_t addr) {
    asm volatile("ldmatrix.sync.aligned.m8n8.x4.shared.b16 {%0,%1,%2,%3}, [%4];"
                 : "=r"(r0), "=r"(r1), "=r"(r2), "=r"(r3) : "r"(addr));
}
__device__ __forceinline__ void mma16816(float* c, uint32_t a0, uint32_t a1, uint32_t a2,
                                         uint32_t a3, uint32_t b0, uint32_t b1) {
    asm volatile(
        "mma.sync.aligned.m16n8k16.row.col.f32.bf16.bf16.f32 "
        "{%0,%1,%2,%3}, {%4,%5,%6,%7}, {%8,%9}, {%0,%1,%2,%3};"
        : "+f"(c[0]), "+f"(c[1]), "+f"(c[2]), "+f"(c[3])
        : "r"(a0), "r"(a1), "r"(a2), "r"(a3), "r"(b0), "r"(b1));
}

// ---------------------------------------------------------------------------
// fp32 -> bf16 hi/lo conversion (hi = rn(x), lo = rn(x - hi))
// ---------------------------------------------------------------------------
__global__ void cvt_hilo(const float4* __restrict__ src, uint2* __restrict__ hi,
                         uint2* __restrict__ lo, int n4) {
    int i = blockIdx.x * blockDim.x + threadIdx.x;
    if (i >= n4) return;
    float4 v = src[i];
    __nv_bfloat16 h0 = __float2bfloat16_rn(v.x);
    __nv_bfloat16 h1 = __float2bfloat16_rn(v.y);
    __nv_bfloat16 h2 = __float2bfloat16_rn(v.z);
    __nv_bfloat16 h3 = __float2bfloat16_rn(v.w);
    __nv_bfloat16 l0 = __float2bfloat16_rn(v.x - __bfloat162float(h0));
    __nv_bfloat16 l1 = __float2bfloat16_rn(v.y - __bfloat162float(h1));
    __nv_bfloat16 l2 = __float2bfloat16_rn(v.z - __bfloat162float(h2));
    __nv_bfloat16 l3 = __float2bfloat16_rn(v.w - __bfloat162float(h3));
    uint2 uh, ul;
    uh.x = ((uint32_t)__bfloat16_as_ushort(h1) << 16) | __bfloat16_as_ushort(h0);
    uh.y = ((uint32_t)__bfloat16_as_ushort(h3) << 16) | __bfloat16_as_ushort(h2);
    ul.x = ((uint32_t)__bfloat16_as_ushort(l1) << 16) | __bfloat16_as_ushort(l0);
    ul.y = ((uint32_t)__bfloat16_as_ushort(l3) << 16) | __bfloat16_as_ushort(l2);
    hi[i] = uh;
    lo[i] = ul;
}

// ---------------------------------------------------------------------------
// mma.sync GEMM: C[M,N] = (Ah+Al)[M,K] * (Bh+Bl)[N,K]^T, dropping Al*Bl.
// CTA tile 128x128, K-chunk 32, double-buffered cp.async.
// 8 warps = 2 (M) x 4 (N); warp tile 64x32.
// Smem tile rows padded to 80B (32 bf16 data + 8 pad) - ldmatrix conflict-free.
// ---------------------------------------------------------------------------
#define TROW 80                       // bytes per smem tile row
#define TILE_BYTES (128 * TROW)       // 10240
#define STAGE_BYTES (4 * TILE_BYTES)  // 40960 : Ah, Al, Bh, Bl
#define GEMM_SMEM (2 * STAGE_BYTES)   // 81920
#define NCHUNK (GK / 32)              // 64

__device__ __forceinline__ void load_stage(uint32_t sbase,
        const __nv_bfloat16* Ah, const __nv_bfloat16* Al,
        const __nv_bfloat16* Bh, const __nv_bfloat16* Bl,
        int m0, int n0, int kc, int tid) {
    const size_t k0 = (size_t)kc * 32;
    const char* bases[4] = {
        (const char*)(Ah + (size_t)m0 * GK + k0),
        (const char*)(Al + (size_t)m0 * GK + k0),
        (const char*)(Bh + (size_t)n0 * GK + k0),
        (const char*)(Bl + (size_t)n0 * GK + k0) };
#pragma unroll
    for (int tile = 0; tile < 4; tile++) {
        const char* bp = bases[tile];
        const uint32_t tb = sbase + tile * TILE_BYTES;
#pragma unroll
        for (int t = 0; t < 2; t++) {
            int g = tid + t * 256;        // 0..511
            int r = g >> 2;               // row 0..127
            int c = (g & 3) * 16;         // byte col 0..48
            cpa16(tb + r * TROW + c, bp + (size_t)r * (GK * 2) + c);
        }
    }
}

__global__ __launch_bounds__(256)
void gemm_mma(const __nv_bfloat16* __restrict__ Ah, const __nv_bfloat16* __restrict__ Al,
              const __nv_bfloat16* __restrict__ Bh, const __nv_bfloat16* __restrict__ Bl,
              float* __restrict__ C) {
    extern __shared__ char smem[];
    const uint32_t sb = smem_u32(smem);
    const int tid = threadIdx.x;
    const int wid = tid >> 5;
    const int lane = tid & 31;
    const int m0 = blockIdx.y * 128;
    const int n0 = blockIdx.x * 128;
    const int m_w = (wid & 1) * 64;
    const int n_w = (wid >> 1) * 32;

    float acc[4][4][4];
#pragma unroll
    for (int i = 0; i < 4; i++)
#pragma unroll
        for (int j = 0; j < 4; j++)
#pragma unroll
            for (int r = 0; r < 4; r++) acc[i][j][r] = 0.f;

    // ldmatrix address components (within a tile)
    const int a_row = lane & 15;                    // m row
    const int a_kb  = (lane >> 4) * 16;             // k byte offset (8 bf16)
    const int b_row = (lane & 7) + ((lane >> 4) << 3);   // n row
    const int b_kb  = ((lane >> 3) & 1) * 16;       // k byte offset

    load_stage(sb, Ah, Al, Bh, Bl, m0, n0, 0, tid);
    cp_commit();

    for (int kc = 0; kc < NCHUNK; kc++) {
        if (kc < NCHUNK - 1) {
            load_stage(sb + ((kc + 1) & 1) * STAGE_BYTES, Ah, Al, Bh, Bl, m0, n0, kc + 1, tid);
            cp_commit();
            cp_wait<1>();
        } else {
            cp_wait<0>();
        }
        __syncthreads();

        const uint32_t stage = sb + (kc & 1) * STAGE_BYTES;
#pragma unroll
        for (int pass = 0; pass < 3; pass++) {
            const uint32_t at = stage + ((pass == 1) ? TILE_BYTES : 0);
            const uint32_t bt = stage + ((pass == 2) ? 3 * TILE_BYTES : 2 * TILE_BYTES);
#pragma unroll
            for (int ks = 0; ks < 2; ks++) {
                uint32_t a[4][4];
#pragma unroll
                for (int mt = 0; mt < 4; mt++) {
                    uint32_t addr = at + (m_w + mt * 16 + a_row) * TROW + ks * 32 + a_kb;
                    ldsm_x4(a[mt][0], a[mt][1], a[mt][2], a[mt][3], addr);
                }
                uint32_t b[2][4];
#pragma unroll
                for (int bq = 0; bq < 2; bq++) {
                    uint32_t addr = bt + (n_w + bq * 16 + b_row) * TROW + ks * 32 + b_kb;
                    ldsm_x4(b[bq][0], b[bq][1], b[bq][2], b[bq][3], addr);
                }
#pragma unroll
                for (int mt = 0; mt < 4; mt++)
#pragma unroll
                    for (int nt = 0; nt < 4; nt++)
                        mma16816(acc[mt][nt], a[mt][0], a[mt][1], a[mt][2], a[mt][3],
                                 b[nt >> 1][(nt & 1) * 2], b[nt >> 1][(nt & 1) * 2 + 1]);
            }
        }
        __syncthreads();
    }

    // Epilogue: c0,c1 -> (row g, col 2t..2t+1); c2,c3 -> row g+8.
    const int g = lane >> 2;
    const int t2 = (lane & 3) * 2;
#pragma unroll
    for (int mt = 0; mt < 4; mt++) {
#pragma unroll
        for (int nt = 0; nt < 4; nt++) {
            int row = m0 + m_w + mt * 16 + g;
            int col = n0 + n_w + nt * 8 + t2;
            *(float2*)&C[(size_t)row * DD + col] = make_float2(acc[mt][nt][0], acc[mt][nt][1]);
            *(float2*)&C[(size_t)(row + 8) * DD + col] = make_float2(acc[mt][nt][2], acc[mt][nt][3]);
        }
    }
}

// ---------------------------------------------------------------------------
// Flash attention, fp32 (unchanged; passed round 1).
// ---------------------------------------------------------------------------
#define QROW 132
#define ATTN_SMEM_FLOATS (3 * 64 * QROW + 64 * 64 + 3 * 64)
#define ATTN_SMEM_BYTES  (ATTN_SMEM_FLOATS * 4)

__global__ __launch_bounds__(256, 1)
void attn_kernel(const float* __restrict__ Q, const float* __restrict__ K,
                 const float* __restrict__ V, float* __restrict__ O) {
    extern __shared__ float sm[];
    float* Qs  = sm;
    float* Ks  = Qs + 64 * QROW;
    float* Vs  = Ks + 64 * QROW;
    float* Ps  = Vs + 64 * QROW;
    float* m_s = Ps + 64 * 64;
    float* l_s = m_s + 64;
    float* sc_s = l_s + 64;

    const int tid = threadIdx.x;
    const int tx = tid & 15;
    const int ty = tid >> 4;
    const int qt = blockIdx.x;
    const int bh = blockIdx.y;
    const int b  = bh >> 4;
    const int h  = bh & 15;

    const size_t qbase = ((size_t)(b * SS + qt * 64)) * DD + (size_t)h * HD;
    const size_t kbase = ((size_t)(b * SS)) * DD + (size_t)h * HD;
    const float scale = 0.08838834764831845f;

#pragma unroll
    for (int l = 0; l < 8; l++) {
        int f = tid + l * 256;
        int r = f >> 5;
        int c4 = (f & 31) << 2;
        float4 v = *(const float4*)&Q[qbase + (size_t)r * DD + c4];
        v.x *= scale; v.y *= scale; v.z *= scale; v.w *= scale;
        *(float4*)&Qs[r * QROW + c4] = v;
    }
    if (tid < 64) { m_s[tid] = -1e30f; l_s[tid] = 0.f; }

    float o[4][8];
#pragma unroll
    for (int i = 0; i < 4; i++)
#pragma unroll
        for (int j = 0; j < 8; j++) o[i][j] = 0.f;

    for (int kt = 0; kt < SS / 64; kt++) {
        const size_t ktile = kbase + (size_t)kt * 64 * DD;
#pragma unroll
        for (int l = 0; l < 8; l++) {
            int f = tid + l * 256;
            int r = f >> 5;
            int c4 = (f & 31) << 2;
            *(float4*)&Ks[r * QROW + c4] = *(const float4*)&K[ktile + (size_t)r * DD + c4];
            *(float4*)&Vs[r * QROW + c4] = *(const float4*)&V[ktile + (size_t)r * DD + c4];
        }
        __syncthreads();

        float s[4][4];
#pragma unroll
        for (int i = 0; i < 4; i++)
#pragma unroll
            for (int j = 0; j < 4; j++) s[i][j] = 0.f;

#pragma unroll 8
        for (int k = 0; k < 128; k += 4) {
            float4 qv[4], kv[4];
#pragma unroll
            for (int i = 0; i < 4; i++)
                qv[i] = *(const float4*)&Qs[(ty * 4 + i) * QROW + k];
#pragma unroll
            for (int j = 0; j < 4; j++)
                kv[j] = *(const float4*)&Ks[(tx * 4 + j) * QROW + k];
#pragma unroll
            for (int i = 0; i < 4; i++)
#pragma unroll
                for (int j = 0; j < 4; j++) {
                    s[i][j] += qv[i].x * kv[j].x;
                    s[i][j] += qv[i].y * kv[j].y;
                    s[i][j] += qv[i].z * kv[j].z;
                    s[i][j] += qv[i].w * kv[j].w;
                }
        }

#pragma unroll
        for (int i = 0; i < 4; i++) {
            const int r = ty * 4 + i;
            float mx = fmaxf(fmaxf(s[i][0], s[i][1]), fmaxf(s[i][2], s[i][3]));
            mx = fmaxf(mx, __shfl_xor_sync(0xffffffffu, mx, 1, 16));
            mx = fmaxf(mx, __shfl_xor_sync(0xffffffffu, mx, 2, 16));
            mx = fmaxf(mx, __shfl_xor_sync(0xffffffffu, mx, 4, 16));
            mx = fmaxf(mx, __shfl_xor_sync(0xffffffffu, mx, 8, 16));
            float m_old = m_s[r];
            float m_new = fmaxf(m_old, mx);
            float sum = 0.f;
#pragma unroll
            for (int j = 0; j < 4; j++) {
                s[i][j] = __expf(s[i][j] - m_new);
                sum += s[i][j];
            }
            sum += __shfl_xor_sync(0xffffffffu, sum, 1, 16);
            sum += __shfl_xor_sync(0xffffffffu, sum, 2, 16);
            sum += __shfl_xor_sync(0xffffffffu, sum, 4, 16);
            sum += __shfl_xor_sync(0xffffffffu, sum, 8, 16);
            if (tx == 0) {
                float sc = __expf(m_old - m_new);
                m_s[r] = m_new;
                sc_s[r] = sc;
                l_s[r] = l_s[r] * sc + sum;
            }
            *(float4*)&Ps[r * 64 + tx * 4] = make_float4(s[i][0], s[i][1], s[i][2], s[i][3]);
        }
        __syncthreads();

#pragma unroll
        for (int i = 0; i < 4; i++) {
            float sc = sc_s[ty * 4 + i];
#pragma unroll
            for (int j = 0; j < 8; j++) o[i][j] *= sc;
        }
#pragma unroll 4
        for (int c = 0; c < 64; c++) {
            float4 v0 = *(const float4*)&Vs[c * QROW + tx * 4];
            float4 v1 = *(const float4*)&Vs[c * QROW + 64 + tx * 4];
#pragma unroll
            for (int i = 0; i < 4; i++) {
                float pv = Ps[(ty * 4 + i) * 64 + c];
                o[i][0] += pv * v0.x; o[i][1] += pv * v0.y;
                o[i][2] += pv * v0.z; o[i][3] += pv * v0.w;
                o[i][4] += pv * v1.x; o[i][5] += pv * v1.y;
                o[i][6] += pv * v1.z; o[i][7] += pv * v1.w;
            }
        }
        __syncthreads();
    }

#pragma unroll
    for (int i = 0; i < 4; i++) {
        const int r = ty * 4 + i;
        float inv = 1.0f / l_s[r];
        size_t orow = qbase + (size_t)r * DD;
        *(float4*)&O[orow + tx * 4] =
            make_float4(o[i][0] * inv, o[i][1] * inv, o[i][2] * inv, o[i][3] * inv);
        *(float4*)&O[orow + 64 + tx * 4] =
            make_float4(o[i][4] * inv, o[i][5] * inv, o[i][6] * inv, o[i][7] * inv);
    }
}

// ---------------------------------------------------------------------------
extern "C" void kernel_launch(void* const* d_in, const int* in_sizes, int n_in,
                              void* d_out, int out_size) {
    const float* x  = (const float*)d_in[0];
    const float* wq = (const float*)d_in[1];
    const float* wk = (const float*)d_in[2];
    const float* wv = (const float*)d_in[3];
    const float* wo = (const float*)d_in[4];
    float* out = (float*)d_out;

    float *q, *k, *v, *att;
    __nv_bfloat16 *xh, *xl, *ah, *al, *wh, *wl;
    cudaGetSymbolAddress((void**)&q,   g_q);
    cudaGetSymbolAddress((void**)&k,   g_k);
    cudaGetSymbolAddress((void**)&v,   g_v);
    cudaGetSymbolAddress((void**)&att, g_att);
    cudaGetSymbolAddress((void**)&xh,  g_xh);
    cudaGetSymbolAddress((void**)&xl,  g_xl);
    cudaGetSymbolAddress((void**)&ah,  g_ah);
    cudaGetSymbolAddress((void**)&al,  g_al);
    cudaGetSymbolAddress((void**)&wh,  g_wh);
    cudaGetSymbolAddress((void**)&wl,  g_wl);

    cudaFuncSetAttribute(attn_kernel, cudaFuncAttributeMaxDynamicSharedMemorySize,
                         ATTN_SMEM_BYTES);
    cudaFuncSetAttribute(gemm_mma, cudaFuncAttributeMaxDynamicSharedMemorySize,
                         GEMM_SMEM);

    const size_t WN = (size_t)DD * DD;
    const int n4x = (MROWS * DD) / 4;
    const int n4w = (DD * DD) / 4;

    // Convert inputs to bf16 hi/lo
    cvt_hilo<<<(n4x + 255) / 256, 256>>>((const float4*)x, (uint2*)xh, (uint2*)xl, n4x);
    cvt_hilo<<<(n4w + 255) / 256, 256>>>((const float4*)wq, (uint2*)(wh + 0 * WN), (uint2*)(wl + 0 * WN), n4w);
    cvt_hilo<<<(n4w + 255) / 256, 256>>>((const float4*)wk, (uint2*)(wh + 1 * WN), (uint2*)(wl + 1 * WN), n4w);
    cvt_hilo<<<(n4w + 255) / 256, 256>>>((const float4*)wv, (uint2*)(wh + 2 * WN), (uint2*)(wl + 2 * WN), n4w);
    cvt_hilo<<<(n4w + 255) / 256, 256>>>((const float4*)wo, (uint2*)(wh + 3 * WN), (uint2*)(wl + 3 * WN), n4w);

    // Projections on tensor cores (mma.sync)
    dim3 ggrid(DD / 128, MROWS / 128);  // (16, 32)
    gemm_mma<<<ggrid, 256, GEMM_SMEM>>>(xh, xl, wh + 0 * WN, wl + 0 * WN, q);
    gemm_mma<<<ggrid, 256, GEMM_SMEM>>>(xh, xl, wh + 1 * WN, wl + 1 * WN, k);
    gemm_mma<<<ggrid, 256, GEMM_SMEM>>>(xh, xl, wh + 2 * WN, wl + 2 * WN, v);

    // Attention (fp32, flash)
    attn_kernel<<<dim3(32, 32), 256, ATTN_SMEM_BYTES>>>(q, k, v, att);

    // Output projection
    cvt_hilo<<<(n4x + 255) / 256, 256>>>((const float4*)att, (uint2*)ah, (uint2*)al, n4x);
    gemm_mma<<<ggrid, 256, GEMM_SMEM>>>(ah, al, wh + 3 * WN, wl + 3 * WN, out);
}

// round 5
// speedup vs baseline: 3.2942x; 2.4088x over previous
#include <cuda_runtime.h>
#include <cuda_bf16.h>
#include <math.h>
#include <stdint.h>

// Problem constants
#define BB 2
#define SS 2048
#define DD 2048
#define HH 16
#define HD 128
#define MROWS (BB*SS)   // 4096
#define GK DD           // 2048

// ---------------------------------------------------------------------------
// Scratch (allocation-free rule: __device__ globals)
// ---------------------------------------------------------------------------
__device__ __nv_bfloat16 g_xh[(size_t)MROWS*DD];
__device__ __nv_bfloat16 g_xl[(size_t)MROWS*DD];
__device__ __nv_bfloat16 g_qh[(size_t)MROWS*DD];
__device__ __nv_bfloat16 g_ql[(size_t)MROWS*DD];
__device__ __nv_bfloat16 g_kh[(size_t)MROWS*DD];
__device__ __nv_bfloat16 g_kl[(size_t)MROWS*DD];
__device__ __nv_bfloat16 g_vh[(size_t)MROWS*DD];
__device__ __nv_bfloat16 g_vl[(size_t)MROWS*DD];
__device__ __nv_bfloat16 g_ah[(size_t)MROWS*DD];
__device__ __nv_bfloat16 g_al[(size_t)MROWS*DD];
__device__ __nv_bfloat16 g_wh[(size_t)4*DD*DD];
__device__ __nv_bfloat16 g_wl[(size_t)4*DD*DD];

// ---------------------------------------------------------------------------
// PTX helpers (sm_100 BASELINE only)
// ---------------------------------------------------------------------------
__device__ __forceinline__ uint32_t smem_u32(const void* p) {
    uint32_t a;
    asm("{ .reg .u64 t; cvta.to.shared.u64 t, %1; cvt.u32.u64 %0, t; }" : "=r"(a) : "l"(p));
    return a;
}
__device__ __forceinline__ void cpa16(uint32_t dst, const void* src) {
    asm volatile("cp.async.cg.shared.global [%0], [%1], 16;\n" :: "r"(dst), "l"(src));
}
__device__ __forceinline__ void cp_commit() {
    asm volatile("cp.async.commit_group;" ::: "memory");
}
template <int N>
__device__ __forceinline__ void cp_wait() {
    asm volatile("cp.async.wait_group %0;" :: "n"(N) : "memory");
}
__device__ __forceinline__ void ldsm_x4(uint32_t& r0, uint32_t& r1, uint32_t& r2, uint32_t& r3,
                                        uint32_t addr) {
    asm volatile("ldmatrix.sync.aligned.m8n8.x4.shared.b16 {%0,%1,%2,%3}, [%4];"
                 : "=r"(r0), "=r"(r1), "=r"(r2), "=r"(r3) : "r"(addr));
}
__device__ __forceinline__ void ldsm_x4_trans(uint32_t& r0, uint32_t& r1, uint32_t& r2, uint32_t& r3,
                                              uint32_t addr) {
    asm volatile("ldmatrix.sync.aligned.m8n8.x4.trans.shared.b16 {%0,%1,%2,%3}, [%4];"
                 : "=r"(r0), "=r"(r1), "=r"(r2), "=r"(r3) : "r"(addr));
}
__device__ __forceinline__ void mma16816(float* c, uint32_t a0, uint32_t a1, uint32_t a2,
                                         uint32_t a3, uint32_t b0, uint32_t b1) {
    asm volatile(
        "mma.sync.aligned.m16n8k16.row.col.f32.bf16.bf16.f32 "
        "{%0,%1,%2,%3}, {%4,%5,%6,%7}, {%8,%9}, {%0,%1,%2,%3};"
        : "+f"(c[0]), "+f"(c[1]), "+f"(c[2]), "+f"(c[3])
        : "r"(a0), "r"(a1), "r"(a2), "r"(a3), "r"(b0), "r"(b1));
}
__device__ __forceinline__ uint32_t pack2bf(float a, float b) {
    return (uint32_t)__bfloat16_as_ushort(__float2bfloat16_rn(a)) |
           ((uint32_t)__bfloat16_as_ushort(__float2bfloat16_rn(b)) << 16);
}
// split (a,b) fp32 into packed bf16 hi pair + lo (residual) pair
__device__ __forceinline__ void split_pack2(float a, float b, uint32_t& hi, uint32_t& lo) {
    __nv_bfloat16 ha = __float2bfloat16_rn(a);
    __nv_bfloat16 hb = __float2bfloat16_rn(b);
    float ra = a - __bfloat162float(ha);
    float rb = b - __bfloat162float(hb);
    hi = (uint32_t)__bfloat16_as_ushort(ha) | ((uint32_t)__bfloat16_as_ushort(hb) << 16);
    lo = (uint32_t)__bfloat16_as_ushort(__float2bfloat16_rn(ra)) |
         ((uint32_t)__bfloat16_as_ushort(__float2bfloat16_rn(rb)) << 16);
}

// ---------------------------------------------------------------------------
// fp32 -> bf16 hi/lo conversion
// ---------------------------------------------------------------------------
__global__ void cvt_hilo(const float4* __restrict__ src, uint2* __restrict__ hi,
                         uint2* __restrict__ lo, int n4) {
    int i = blockIdx.x * blockDim.x + threadIdx.x;
    if (i >= n4) return;
    float4 v = src[i];
    uint2 uh, ul;
    split_pack2(v.x, v.y, uh.x, ul.x);
    split_pack2(v.z, v.w, uh.y, ul.y);
    hi[i] = uh;
    lo[i] = ul;
}

// ---------------------------------------------------------------------------
// mma.sync GEMM: C = (Ah+Al)*(Bh+Bl)^T, dropping Al*Bl.
// 128x128 CTA tile, K-chunk 32, double-buffered cp.async, 8 warps (2Mx4N).
// EPI 0: fp32 output. EPI 1: bf16 hi/lo output.
// ---------------------------------------------------------------------------
#define TROW 80
#define TILE_BYTES (128 * TROW)
#define STAGE_BYTES (4 * TILE_BYTES)
#define GEMM_SMEM (2 * STAGE_BYTES)   // 81920
#define NCHUNK (GK / 32)

__device__ __forceinline__ void load_stage(uint32_t sbase,
        const __nv_bfloat16* Ah, const __nv_bfloat16* Al,
        const __nv_bfloat16* Bh, const __nv_bfloat16* Bl,
        int m0, int n0, int kc, int tid) {
    const size_t k0 = (size_t)kc * 32;
    const char* bases[4] = {
        (const char*)(Ah + (size_t)m0 * GK + k0),
        (const char*)(Al + (size_t)m0 * GK + k0),
        (const char*)(Bh + (size_t)n0 * GK + k0),
        (const char*)(Bl + (size_t)n0 * GK + k0) };
#pragma unroll
    for (int tile = 0; tile < 4; tile++) {
        const char* bp = bases[tile];
        const uint32_t tb = sbase + tile * TILE_BYTES;
#pragma unroll
        for (int t = 0; t < 2; t++) {
            int g = tid + t * 256;
            int r = g >> 2;
            int c = (g & 3) * 16;
            cpa16(tb + r * TROW + c, bp + (size_t)r * (GK * 2) + c);
        }
    }
}

template<int EPI>
__global__ __launch_bounds__(256, 2)
void gemm_mma(const __nv_bfloat16* __restrict__ Ah, const __nv_bfloat16* __restrict__ Al,
              const __nv_bfloat16* __restrict__ Bh, const __nv_bfloat16* __restrict__ Bl,
              float* __restrict__ C,
              __nv_bfloat16* __restrict__ Ch, __nv_bfloat16* __restrict__ Cl) {
    extern __shared__ char smem[];
    const uint32_t sb = smem_u32(smem);
    const int tid = threadIdx.x;
    const int wid = tid >> 5;
    const int lane = tid & 31;
    const int m0 = blockIdx.y * 128;
    const int n0 = blockIdx.x * 128;
    const int m_w = (wid & 1) * 64;
    const int n_w = (wid >> 1) * 32;

    float acc[4][4][4];
#pragma unroll
    for (int i = 0; i < 4; i++)
#pragma unroll
        for (int j = 0; j < 4; j++)
#pragma unroll
            for (int r = 0; r < 4; r++) acc[i][j][r] = 0.f;

    const int a_row = lane & 15;
    const int a_kb  = (lane >> 4) * 16;
    const int b_row = (lane & 7) + ((lane >> 4) << 3);
    const int b_kb  = ((lane >> 3) & 1) * 16;

    load_stage(sb, Ah, Al, Bh, Bl, m0, n0, 0, tid);
    cp_commit();

    for (int kc = 0; kc < NCHUNK; kc++) {
        if (kc < NCHUNK - 1) {
            load_stage(sb + ((kc + 1) & 1) * STAGE_BYTES, Ah, Al, Bh, Bl, m0, n0, kc + 1, tid);
            cp_commit();
            cp_wait<1>();
        } else {
            cp_wait<0>();
        }
        __syncthreads();

        const uint32_t stage = sb + (kc & 1) * STAGE_BYTES;
#pragma unroll
        for (int pass = 0; pass < 3; pass++) {
            const uint32_t at = stage + ((pass == 1) ? TILE_BYTES : 0);
            const uint32_t bt = stage + ((pass == 2) ? 3 * TILE_BYTES : 2 * TILE_BYTES);
#pragma unroll
            for (int ks = 0; ks < 2; ks++) {
                uint32_t a[4][4];
#pragma unroll
                for (int mt = 0; mt < 4; mt++) {
                    uint32_t addr = at + (m_w + mt * 16 + a_row) * TROW + ks * 32 + a_kb;
                    ldsm_x4(a[mt][0], a[mt][1], a[mt][2], a[mt][3], addr);
                }
                uint32_t b[2][4];
#pragma unroll
                for (int bq = 0; bq < 2; bq++) {
                    uint32_t addr = bt + (n_w + bq * 16 + b_row) * TROW + ks * 32 + b_kb;
                    ldsm_x4(b[bq][0], b[bq][1], b[bq][2], b[bq][3], addr);
                }
#pragma unroll
                for (int mt = 0; mt < 4; mt++)
#pragma unroll
                    for (int nt = 0; nt < 4; nt++)
                        mma16816(acc[mt][nt], a[mt][0], a[mt][1], a[mt][2], a[mt][3],
                                 b[nt >> 1][(nt & 1) * 2], b[nt >> 1][(nt & 1) * 2 + 1]);
            }
        }
        __syncthreads();
    }

    const int g = lane >> 2;
    const int t2 = (lane & 3) * 2;
#pragma unroll
    for (int mt = 0; mt < 4; mt++) {
#pragma unroll
        for (int nt = 0; nt < 4; nt++) {
            int row = m0 + m_w + mt * 16 + g;
            int col = n0 + n_w + nt * 8 + t2;
            if (EPI == 0) {
                *(float2*)&C[(size_t)row * DD + col] = make_float2(acc[mt][nt][0], acc[mt][nt][1]);
                *(float2*)&C[(size_t)(row + 8) * DD + col] = make_float2(acc[mt][nt][2], acc[mt][nt][3]);
            } else {
                uint32_t hi, lo;
                split_pack2(acc[mt][nt][0], acc[mt][nt][1], hi, lo);
                *(uint32_t*)(Ch + (size_t)row * DD + col) = hi;
                *(uint32_t*)(Cl + (size_t)row * DD + col) = lo;
                split_pack2(acc[mt][nt][2], acc[mt][nt][3], hi, lo);
                *(uint32_t*)(Ch + (size_t)(row + 8) * DD + col) = hi;
                *(uint32_t*)(Cl + (size_t)(row + 8) * DD + col) = lo;
            }
        }
    }
}

// ---------------------------------------------------------------------------
// Flash attention on mma.sync, hi/lo bf16 3-pass for both QK^T and PV.
// CTA: 128 q rows x (64-key tiles), 8 warps. S layout 4Mx2N (warp 32x32),
// O layout 4Mx2N (warp 32x64) -- same M split so per-row state stays in-warp.
// Smem rows: Q/K/V padded to 272B, P padded to 144B (ldmatrix conflict-free).
// ---------------------------------------------------------------------------
#define AQROW 272
#define PROWB 144
#define OFF_QH   0
#define OFF_QL   34816
#define OFF_K    69632           // 2 stages x (Kh 17408 + Kl 17408)
#define KSTAGE   34816
#define OFF_VH   139264
#define OFF_VL   156672
#define OFF_PH   174080
#define OFF_PL   192512
#define OFF_PMAX 210944          // float[2][128]
#define OFF_PSUM 211968          // float[2][128]
#define ATTN_SMEM 212992

__device__ __forceinline__ void load_kv64(uint32_t dsth, uint32_t dstl,
        const __nv_bfloat16* Gh, const __nv_bfloat16* Gl, size_t gbase, int tid) {
#pragma unroll
    for (int gr = tid; gr < 1024; gr += 256) {
        int r = gr >> 4;
        int c = (gr & 15) * 16;
        size_t go = gbase + (size_t)r * DD;
        cpa16(dsth + r * AQROW + c, (const char*)(Gh + go) + c);
        cpa16(dstl + r * AQROW + c, (const char*)(Gl + go) + c);
    }
}

__global__ __launch_bounds__(256, 1)
void attn_mma(const __nv_bfloat16* __restrict__ Qh_g, const __nv_bfloat16* __restrict__ Ql_g,
              const __nv_bfloat16* __restrict__ Kh_g, const __nv_bfloat16* __restrict__ Kl_g,
              const __nv_bfloat16* __restrict__ Vh_g, const __nv_bfloat16* __restrict__ Vl_g,
              __nv_bfloat16* __restrict__ Oh_g, __nv_bfloat16* __restrict__ Ol_g) {
    extern __shared__ char smem[];
    const uint32_t sb = smem_u32(smem);
    float* pmaxf = (float*)(smem + OFF_PMAX);
    float* psumf = (float*)(smem + OFF_PSUM);

    const int tid = threadIdx.x;
    const int wid = tid >> 5;
    const int lane = tid & 31;
    const int qt = blockIdx.x;           // 0..15
    const int bh = blockIdx.y;           // 0..31
    const int b  = bh >> 4;
    const int h  = bh & 15;

    const int m_w = (wid & 3) * 32;      // warp M base (same for S and O)
    const int nh  = wid >> 2;            // warp N half (S: 32 cols, O: 64 cols)
    const int g   = lane >> 2;
    const int tc  = lane & 3;
    const int a_row = lane & 15;
    const int a_kb  = (lane >> 4) * 16;
    const int b_row = (lane & 7) + ((lane >> 4) << 3);
    const int b_kb  = ((lane >> 3) & 1) * 16;
    const int v_row = (lane & 7) + (((lane >> 3) & 1) << 3);
    const int v_cb  = (lane >> 4) * 16;

    const size_t qgbase = ((size_t)(b * SS + qt * 128)) * DD + (size_t)h * HD;
    const size_t kgbase = ((size_t)(b * SS)) * DD + (size_t)h * HD;

    // Q tile (128 x 128 hd), hi+lo
#pragma unroll
    for (int gr = tid; gr < 2048; gr += 256) {
        int r = gr >> 4;
        int c = (gr & 15) * 16;
        size_t go = qgbase + (size_t)r * DD;
        cpa16(sb + OFF_QH + r * AQROW + c, (const char*)(Qh_g + go) + c);
        cpa16(sb + OFF_QL + r * AQROW + c, (const char*)(Ql_g + go) + c);
    }
    load_kv64(sb + OFF_K, sb + OFF_K + 17408, Kh_g, Kl_g, kgbase, tid);
    cp_commit();   // group {Q, K0}

    float o[2][8][4];
#pragma unroll
    for (int mt = 0; mt < 2; mt++)
#pragma unroll
        for (int nt = 0; nt < 8; nt++)
#pragma unroll
            for (int c = 0; c < 4; c++) o[mt][nt][c] = 0.f;
    float m_r[2][2] = {{-1e30f, -1e30f}, {-1e30f, -1e30f}};
    float l_r[2][2] = {{0.f, 0.f}, {0.f, 0.f}};

    const float SCALE = 0.08838834764831845f;

    for (int kt = 0; kt < SS / 64; kt++) {
        if (kt < SS / 64 - 1) {
            uint32_t kst_next = sb + OFF_K + ((kt + 1) & 1) * KSTAGE;
            load_kv64(kst_next, kst_next + 17408, Kh_g, Kl_g,
                      kgbase + (size_t)(kt + 1) * 64 * DD, tid);
            cp_commit();
        }
        if (kt == 0) { cp_wait<1>(); __syncthreads(); }

        const uint32_t kst = sb + OFF_K + (kt & 1) * KSTAGE;

        // ---- S = (Qh+Ql)(Kh+Kl)^T (3 passes), S tile 128x64 ----
        float s_acc[2][4][4];
#pragma unroll
        for (int mt = 0; mt < 2; mt++)
#pragma unroll
            for (int nt = 0; nt < 4; nt++)
#pragma unroll
                for (int c = 0; c < 4; c++) s_acc[mt][nt][c] = 0.f;

#pragma unroll
        for (int ks = 0; ks < 8; ks++) {
            uint32_t bk[2][4], aq[2][4];
#pragma unroll
            for (int n16 = 0; n16 < 2; n16++)
                ldsm_x4(bk[n16][0], bk[n16][1], bk[n16][2], bk[n16][3],
                        kst + (nh * 32 + n16 * 16 + b_row) * AQROW + ks * 32 + b_kb);
#pragma unroll
            for (int mt = 0; mt < 2; mt++)
                ldsm_x4(aq[mt][0], aq[mt][1], aq[mt][2], aq[mt][3],
                        sb + OFF_QH + (m_w + mt * 16 + a_row) * AQROW + ks * 32 + a_kb);
            // Qh * Kh
#pragma unroll
            for (int mt = 0; mt < 2; mt++)
#pragma unroll
                for (int nt = 0; nt < 4; nt++)
                    mma16816(s_acc[mt][nt], aq[mt][0], aq[mt][1], aq[mt][2], aq[mt][3],
                             bk[nt >> 1][(nt & 1) * 2], bk[nt >> 1][(nt & 1) * 2 + 1]);
            // Ql * Kh
#pragma unroll
            for (int mt = 0; mt < 2; mt++) {
                uint32_t al4[4];
                ldsm_x4(al4[0], al4[1], al4[2], al4[3],
                        sb + OFF_QL + (m_w + mt * 16 + a_row) * AQROW + ks * 32 + a_kb);
#pragma unroll
                for (int nt = 0; nt < 4; nt++)
                    mma16816(s_acc[mt][nt], al4[0], al4[1], al4[2], al4[3],
                             bk[nt >> 1][(nt & 1) * 2], bk[nt >> 1][(nt & 1) * 2 + 1]);
            }
            // Qh * Kl
#pragma unroll
            for (int n16 = 0; n16 < 2; n16++)
                ldsm_x4(bk[n16][0], bk[n16][1], bk[n16][2], bk[n16][3],
                        kst + 17408 + (nh * 32 + n16 * 16 + b_row) * AQROW + ks * 32 + b_kb);
#pragma unroll
            for (int mt = 0; mt < 2; mt++)
#pragma unroll
                for (int nt = 0; nt < 4; nt++)
                    mma16816(s_acc[mt][nt], aq[mt][0], aq[mt][1], aq[mt][2], aq[mt][3],
                             bk[nt >> 1][(nt & 1) * 2], bk[nt >> 1][(nt & 1) * 2 + 1]);
        }

#pragma unroll
        for (int mt = 0; mt < 2; mt++)
#pragma unroll
            for (int nt = 0; nt < 4; nt++)
#pragma unroll
                for (int c = 0; c < 4; c++) s_acc[mt][nt][c] *= SCALE;

        // ---- partial row max -> smem ----
#pragma unroll
        for (int mt = 0; mt < 2; mt++)
#pragma unroll
            for (int hh = 0; hh < 2; hh++) {
                float mx = fmaxf(s_acc[mt][0][hh * 2], s_acc[mt][0][hh * 2 + 1]);
#pragma unroll
                for (int nt = 1; nt < 4; nt++)
                    mx = fmaxf(mx, fmaxf(s_acc[mt][nt][hh * 2], s_acc[mt][nt][hh * 2 + 1]));
                mx = fmaxf(mx, __shfl_xor_sync(0xffffffffu, mx, 1));
                mx = fmaxf(mx, __shfl_xor_sync(0xffffffffu, mx, 2));
                if (tc == 0) pmaxf[nh * 128 + m_w + mt * 16 + hh * 8 + g] = mx;
            }
        __syncthreads();   // sync#1

        // issue V(kt) load (buffer free: all warps finished PV(kt-1) before sync#1)
        load_kv64(sb + OFF_VH, sb + OFF_VL, Vh_g, Vl_g,
                  kgbase + (size_t)kt * 64 * DD, tid);
        cp_commit();

        // ---- softmax: m_new, exp, P hi/lo -> smem, partial sums, O rescale ----
        float sc_f[2][2];
#pragma unroll
        for (int mt = 0; mt < 2; mt++)
#pragma unroll
            for (int hh = 0; hh < 2; hh++) {
                const int row = m_w + mt * 16 + hh * 8 + g;
                float mtile = fmaxf(pmaxf[row], pmaxf[128 + row]);
                float m_new = fmaxf(m_r[mt][hh], mtile);
                float sc = __expf(m_r[mt][hh] - m_new);
                sc_f[mt][hh] = sc;
                m_r[mt][hh] = m_new;
                float sum = 0.f;
#pragma unroll
                for (int nt = 0; nt < 4; nt++) {
                    float p0 = __expf(s_acc[mt][nt][hh * 2] - m_new);
                    float p1 = __expf(s_acc[mt][nt][hh * 2 + 1] - m_new);
                    sum += p0 + p1;
                    uint32_t hi, lo;
                    split_pack2(p0, p1, hi, lo);
                    int cbyte = row * PROWB + (nh * 32 + nt * 8 + 2 * tc) * 2;
                    *(uint32_t*)(smem + OFF_PH + cbyte) = hi;
                    *(uint32_t*)(smem + OFF_PL + cbyte) = lo;
                }
                sum += __shfl_xor_sync(0xffffffffu, sum, 1);
                sum += __shfl_xor_sync(0xffffffffu, sum, 2);
                if (tc == 0) psumf[nh * 128 + row] = sum;
#pragma unroll
                for (int nt = 0; nt < 8; nt++) {
                    o[mt][nt][hh * 2]     *= sc;
                    o[mt][nt][hh * 2 + 1] *= sc;
                }
            }
        cp_wait<0>();      // V(kt) (+K(kt+1)) arrived
        __syncthreads();   // sync#2: P, psum, V visible

#pragma unroll
        for (int mt = 0; mt < 2; mt++)
#pragma unroll
            for (int hh = 0; hh < 2; hh++) {
                const int row = m_w + mt * 16 + hh * 8 + g;
                l_r[mt][hh] = l_r[mt][hh] * sc_f[mt][hh] + psumf[row] + psumf[128 + row];
            }

        // ---- O += (Ph+Pl)(Vh+Vl) (3 passes), warp tile 32x64 ----
#pragma unroll
        for (int ks = 0; ks < 4; ks++) {
            uint32_t bv[4][4], ap[2][4];
#pragma unroll
            for (int n16 = 0; n16 < 4; n16++)
                ldsm_x4_trans(bv[n16][0], bv[n16][1], bv[n16][2], bv[n16][3],
                              sb + OFF_VH + (ks * 16 + v_row) * AQROW
                                 + (nh * 64 + n16 * 16) * 2 + v_cb);
#pragma unroll
            for (int mt = 0; mt < 2; mt++)
                ldsm_x4(ap[mt][0], ap[mt][1], ap[mt][2], ap[mt][3],
                        sb + OFF_PH + (m_w + mt * 16 + a_row) * PROWB + ks * 32 + a_kb);
            // Ph * Vh
#pragma unroll
            for (int mt = 0; mt < 2; mt++)
#pragma unroll
                for (int nt = 0; nt < 8; nt++)
                    mma16816(o[mt][nt], ap[mt][0], ap[mt][1], ap[mt][2], ap[mt][3],
                             bv[nt >> 1][(nt & 1) * 2], bv[nt >> 1][(nt & 1) * 2 + 1]);
            // Pl * Vh
#pragma unroll
            for (int mt = 0; mt < 2; mt++) {
                uint32_t apl[4];
                ldsm_x4(apl[0], apl[1], apl[2], apl[3],
                        sb + OFF_PL + (m_w + mt * 16 + a_row) * PROWB + ks * 32 + a_kb);
#pragma unroll
                for (int nt = 0; nt < 8; nt++)
                    mma16816(o[mt][nt], apl[0], apl[1], apl[2], apl[3],
                             bv[nt >> 1][(nt & 1) * 2], bv[nt >> 1][(nt & 1) * 2 + 1]);
            }
            // Ph * Vl
#pragma unroll
            for (int n16 = 0; n16 < 4; n16++)
                ldsm_x4_trans(bv[n16][0], bv[n16][1], bv[n16][2], bv[n16][3],
                              sb + OFF_VL + (ks * 16 + v_row) * AQROW
                                 + (nh * 64 + n16 * 16) * 2 + v_cb);
#pragma unroll
            for (int mt = 0; mt < 2; mt++)
#pragma unroll
                for (int nt = 0; nt < 8; nt++)
                    mma16816(o[mt][nt], ap[mt][0], ap[mt][1], ap[mt][2], ap[mt][3],
                             bv[nt >> 1][(nt & 1) * 2], bv[nt >> 1][(nt & 1) * 2 + 1]);
        }
    }

    // ---- epilogue: normalize, split hi/lo, store ----
#pragma unroll
    for (int mt = 0; mt < 2; mt++)
#pragma unroll
        for (int hh = 0; hh < 2; hh++) {
            const float inv = 1.0f / l_r[mt][hh];
            const size_t row = (size_t)(b * SS + qt * 128 + m_w + mt * 16 + hh * 8 + g);
#pragma unroll
            for (int nt = 0; nt < 8; nt++) {
                int col = h * HD + nh * 64 + nt * 8 + 2 * tc;
                uint32_t hi, lo;
                split_pack2(o[mt][nt][hh * 2] * inv, o[mt][nt][hh * 2 + 1] * inv, hi, lo);
                *(uint32_t*)(Oh_g + row * DD + col) = hi;
                *(uint32_t*)(Ol_g + row * DD + col) = lo;
            }
        }
}

// ---------------------------------------------------------------------------
extern "C" void kernel_launch(void* const* d_in, const int* in_sizes, int n_in,
                              void* d_out, int out_size) {
    const float* x  = (const float*)d_in[0];
    const float* wq = (const float*)d_in[1];
    const float* wk = (const float*)d_in[2];
    const float* wv = (const float*)d_in[3];
    const float* wo = (const float*)d_in[4];
    float* out = (float*)d_out;

    __nv_bfloat16 *xh, *xl, *qh, *ql, *kh, *kl, *vh, *vl, *ah, *al, *wh, *wl;
    cudaGetSymbolAddress((void**)&xh, g_xh);
    cudaGetSymbolAddress((void**)&xl, g_xl);
    cudaGetSymbolAddress((void**)&qh, g_qh);
    cudaGetSymbolAddress((void**)&ql, g_ql);
    cudaGetSymbolAddress((void**)&kh, g_kh);
    cudaGetSymbolAddress((void**)&kl, g_kl);
    cudaGetSymbolAddress((void**)&vh, g_vh);
    cudaGetSymbolAddress((void**)&vl, g_vl);
    cudaGetSymbolAddress((void**)&ah, g_ah);
    cudaGetSymbolAddress((void**)&al, g_al);
    cudaGetSymbolAddress((void**)&wh, g_wh);
    cudaGetSymbolAddress((void**)&wl, g_wl);

    cudaFuncSetAttribute(gemm_mma<0>, cudaFuncAttributeMaxDynamicSharedMemorySize, GEMM_SMEM);
    cudaFuncSetAttribute(gemm_mma<1>, cudaFuncAttributeMaxDynamicSharedMemorySize, GEMM_SMEM);
    cudaFuncSetAttribute(attn_mma, cudaFuncAttributeMaxDynamicSharedMemorySize, ATTN_SMEM);

    const size_t WN = (size_t)DD * DD;
    const int n4x = (MROWS * DD) / 4;
    const int n4w = (DD * DD) / 4;

    cvt_hilo<<<(n4x + 255) / 256, 256>>>((const float4*)x, (uint2*)xh, (uint2*)xl, n4x);
    cvt_hilo<<<(n4w + 255) / 256, 256>>>((const float4*)wq, (uint2*)(wh + 0 * WN), (uint2*)(wl + 0 * WN), n4w);
    cvt_hilo<<<(n4w + 255) / 256, 256>>>((const float4*)wk, (uint2*)(wh + 1 * WN), (uint2*)(wl + 1 * WN), n4w);
    cvt_hilo<<<(n4w + 255) / 256, 256>>>((const float4*)wv, (uint2*)(wh + 2 * WN), (uint2*)(wl + 2 * WN), n4w);
    cvt_hilo<<<(n4w + 255) / 256, 256>>>((const float4*)wo, (uint2*)(wh + 3 * WN), (uint2*)(wl + 3 * WN), n4w);

    dim3 ggrid(DD / 128, MROWS / 128);  // (16, 32)
    gemm_mma<1><<<ggrid, 256, GEMM_SMEM>>>(xh, xl, wh + 0 * WN, wl + 0 * WN, nullptr, qh, ql);
    gemm_mma<1><<<ggrid, 256, GEMM_SMEM>>>(xh, xl, wh + 1 * WN, wl + 1 * WN, nullptr, kh, kl);
    gemm_mma<1><<<ggrid, 256, GEMM_SMEM>>>(xh, xl, wh + 2 * WN, wl + 2 * WN, nullptr, vh, vl);

    attn_mma<<<dim3(16, 32), 256, ATTN_SMEM>>>(qh, ql, kh, kl, vh, vl, ah, al);

    gemm_mma<0><<<ggrid, 256, GEMM_SMEM>>>(ah, al, wh + 3 * WN, wl + 3 * WN, out, nullptr, nullptr);
}

// round 7
// speedup vs baseline: 3.4405x; 1.0444x over previous
#include <cuda_runtime.h>
#include <cuda_bf16.h>
#include <math.h>
#include <stdint.h>

// Problem constants
#define BB 2
#define SS 2048
#define DD 2048
#define HH 16
#define HD 128
#define MROWS (BB*SS)   // 4096
#define GK DD           // 2048

// ---------------------------------------------------------------------------
// Scratch (allocation-free rule: __device__ globals)
// ---------------------------------------------------------------------------
__device__ __nv_bfloat16 g_xh[(size_t)MROWS*DD];
__device__ __nv_bfloat16 g_xl[(size_t)MROWS*DD];
__device__ __nv_bfloat16 g_qh[(size_t)MROWS*DD];
__device__ __nv_bfloat16 g_ql[(size_t)MROWS*DD];
__device__ __nv_bfloat16 g_kh[(size_t)MROWS*DD];
__device__ __nv_bfloat16 g_kl[(size_t)MROWS*DD];
__device__ __nv_bfloat16 g_vh[(size_t)MROWS*DD];
__device__ __nv_bfloat16 g_vl[(size_t)MROWS*DD];
__device__ __nv_bfloat16 g_ah[(size_t)MROWS*DD];
__device__ __nv_bfloat16 g_al[(size_t)MROWS*DD];
__device__ __nv_bfloat16 g_wh[(size_t)4*DD*DD];
__device__ __nv_bfloat16 g_wl[(size_t)4*DD*DD];

// ---------------------------------------------------------------------------
// PTX helpers (sm_100 BASELINE only)
// ---------------------------------------------------------------------------
__device__ __forceinline__ uint32_t smem_u32(const void* p) {
    uint32_t a;
    asm("{ .reg .u64 t; cvta.to.shared.u64 t, %1; cvt.u32.u64 %0, t; }" : "=r"(a) : "l"(p));
    return a;
}
__device__ __forceinline__ void cpa16(uint32_t dst, const void* src) {
    asm volatile("cp.async.cg.shared.global [%0], [%1], 16;\n" :: "r"(dst), "l"(src));
}
__device__ __forceinline__ void cp_commit() {
    asm volatile("cp.async.commit_group;" ::: "memory");
}
template <int N>
__device__ __forceinline__ void cp_wait() {
    asm volatile("cp.async.wait_group %0;" :: "n"(N) : "memory");
}
__device__ __forceinline__ void ldsm_x4(uint32_t& r0, uint32_t& r1, uint32_t& r2, uint32_t& r3,
                                        uint32_t addr) {
    asm volatile("ldmatrix.sync.aligned.m8n8.x4.shared.b16 {%0,%1,%2,%3}, [%4];"
                 : "=r"(r0), "=r"(r1), "=r"(r2), "=r"(r3) : "r"(addr));
}
__device__ __forceinline__ void ldsm_x4_trans(uint32_t& r0, uint32_t& r1, uint32_t& r2, uint32_t& r3,
                                              uint32_t addr) {
    asm volatile("ldmatrix.sync.aligned.m8n8.x4.trans.shared.b16 {%0,%1,%2,%3}, [%4];"
                 : "=r"(r0), "=r"(r1), "=r"(r2), "=r"(r3) : "r"(addr));
}
__device__ __forceinline__ void mma16816(float* c, uint32_t a0, uint32_t a1, uint32_t a2,
                                         uint32_t a3, uint32_t b0, uint32_t b1) {
    asm volatile(
        "mma.sync.aligned.m16n8k16.row.col.f32.bf16.bf16.f32 "
        "{%0,%1,%2,%3}, {%4,%5,%6,%7}, {%8,%9}, {%0,%1,%2,%3};"
        : "+f"(c[0]), "+f"(c[1]), "+f"(c[2]), "+f"(c[3])
        : "r"(a0), "r"(a1), "r"(a2), "r"(a3), "r"(b0), "r"(b1));
}
// split (a,b) fp32 into packed bf16 hi pair + lo (residual) pair
__device__ __forceinline__ void split_pack2(float a, float b, uint32_t& hi, uint32_t& lo) {
    __nv_bfloat16 ha = __float2bfloat16_rn(a);
    __nv_bfloat16 hb = __float2bfloat16_rn(b);
    float ra = a - __bfloat162float(ha);
    float rb = b - __bfloat162float(hb);
    hi = (uint32_t)__bfloat16_as_ushort(ha) | ((uint32_t)__bfloat16_as_ushort(hb) << 16);
    lo = (uint32_t)__bfloat16_as_ushort(__float2bfloat16_rn(ra)) |
         ((uint32_t)__bfloat16_as_ushort(__float2bfloat16_rn(rb)) << 16);
}

// ---------------------------------------------------------------------------
// fp32 -> bf16 hi/lo conversion
// ---------------------------------------------------------------------------
__global__ void cvt_hilo(const float4* __restrict__ src, uint2* __restrict__ hi,
                         uint2* __restrict__ lo, int n4) {
    int i = blockIdx.x * blockDim.x + threadIdx.x;
    if (i >= n4) return;
    float4 v = src[i];
    uint2 uh, ul;
    split_pack2(v.x, v.y, uh.x, ul.x);
    split_pack2(v.z, v.w, uh.y, ul.y);
    hi[i] = uh;
    lo[i] = ul;
}

// ---------------------------------------------------------------------------
// mma.sync GEMM: C = (Ah+Al)*(Bh+Bl)^T, dropping Al*Bl.
// 128x128 CTA tile, K-chunk 32, double-buffered cp.async, 8 warps (2Mx4N).
// ks-outer mainloop: A-hi and B-hi fragments reused across the 3 passes.
// ---------------------------------------------------------------------------
#define TROW 80
#define TILE_BYTES (128 * TROW)
#define STAGE_BYTES (4 * TILE_BYTES)
#define GEMM_SMEM (2 * STAGE_BYTES)   // 81920
#define NCHUNK (GK / 32)

__device__ __forceinline__ void load_stage(uint32_t sbase,
        const __nv_bfloat16* Ah, const __nv_bfloat16* Al,
        const __nv_bfloat16* Bh, const __nv_bfloat16* Bl,
        int m0, int n0, int kc, int tid) {
    const size_t k0 = (size_t)kc * 32;
    const char* bases[4] = {
        (const char*)(Ah + (size_t)m0 * GK + k0),
        (const char*)(Al + (size_t)m0 * GK + k0),
        (const char*)(Bh + (size_t)n0 * GK + k0),
        (const char*)(Bl + (size_t)n0 * GK + k0) };
#pragma unroll
    for (int tile = 0; tile < 4; tile++) {
        const char* bp = bases[tile];
        const uint32_t tb = sbase + tile * TILE_BYTES;
#pragma unroll
        for (int t = 0; t < 2; t++) {
            int g = tid + t * 256;
            int r = g >> 2;
            int c = (g & 3) * 16;
            cpa16(tb + r * TROW + c, bp + (size_t)r * (GK * 2) + c);
        }
    }
}

template<int EPI>
__global__ __launch_bounds__(256, 2)
void gemm_mma(const __nv_bfloat16* __restrict__ Ah, const __nv_bfloat16* __restrict__ Al,
              const __nv_bfloat16* __restrict__ Bh, const __nv_bfloat16* __restrict__ Bl,
              float* __restrict__ C,
              __nv_bfloat16* __restrict__ Ch, __nv_bfloat16* __restrict__ Cl) {
    extern __shared__ char smem[];
    const uint32_t sb = smem_u32(smem);
    const int tid = threadIdx.x;
    const int wid = tid >> 5;
    const int lane = tid & 31;
    const int m0 = blockIdx.y * 128;
    const int n0 = blockIdx.x * 128;
    const int m_w = (wid & 1) * 64;
    const int n_w = (wid >> 1) * 32;

    float acc[4][4][4];
#pragma unroll
    for (int i = 0; i < 4; i++)
#pragma unroll
        for (int j = 0; j < 4; j++)
#pragma unroll
            for (int r = 0; r < 4; r++) acc[i][j][r] = 0.f;

    const int a_row = lane & 15;
    const int a_kb  = (lane >> 4) * 16;
    const int b_row = (lane & 7) + ((lane >> 4) << 3);
    const int b_kb  = ((lane >> 3) & 1) * 16;

    load_stage(sb, Ah, Al, Bh, Bl, m0, n0, 0, tid);
    cp_commit();

    for (int kc = 0; kc < NCHUNK; kc++) {
        if (kc < NCHUNK - 1) {
            load_stage(sb + ((kc + 1) & 1) * STAGE_BYTES, Ah, Al, Bh, Bl, m0, n0, kc + 1, tid);
            cp_commit();
            cp_wait<1>();
        } else {
            cp_wait<0>();
        }
        __syncthreads();

        const uint32_t stage = sb + (kc & 1) * STAGE_BYTES;
        const uint32_t atH = stage;
        const uint32_t atL = stage + TILE_BYTES;
        const uint32_t btH = stage + 2 * TILE_BYTES;
        const uint32_t btL = stage + 3 * TILE_BYTES;
#pragma unroll
        for (int ks = 0; ks < 2; ks++) {
            uint32_t aq[4][4], bh[2][4];
#pragma unroll
            for (int mt = 0; mt < 4; mt++)
                ldsm_x4(aq[mt][0], aq[mt][1], aq[mt][2], aq[mt][3],
                        atH + (m_w + mt * 16 + a_row) * TROW + ks * 32 + a_kb);
#pragma unroll
            for (int bq = 0; bq < 2; bq++)
                ldsm_x4(bh[bq][0], bh[bq][1], bh[bq][2], bh[bq][3],
                        btH + (n_w + bq * 16 + b_row) * TROW + ks * 32 + b_kb);
            // Ah * Bh
#pragma unroll
            for (int mt = 0; mt < 4; mt++)
#pragma unroll
                for (int nt = 0; nt < 4; nt++)
                    mma16816(acc[mt][nt], aq[mt][0], aq[mt][1], aq[mt][2], aq[mt][3],
                             bh[nt >> 1][(nt & 1) * 2], bh[nt >> 1][(nt & 1) * 2 + 1]);
            // Ah * Bl
            {
                uint32_t bl[2][4];
#pragma unroll
                for (int bq = 0; bq < 2; bq++)
                    ldsm_x4(bl[bq][0], bl[bq][1], bl[bq][2], bl[bq][3],
                            btL + (n_w + bq * 16 + b_row) * TROW + ks * 32 + b_kb);
#pragma unroll
                for (int mt = 0; mt < 4; mt++)
#pragma unroll
                    for (int nt = 0; nt < 4; nt++)
                        mma16816(acc[mt][nt], aq[mt][0], aq[mt][1], aq[mt][2], aq[mt][3],
                                 bl[nt >> 1][(nt & 1) * 2], bl[nt >> 1][(nt & 1) * 2 + 1]);
            }
            // Al * Bh
            {
                uint32_t al[4];
#pragma unroll
                for (int mt = 0; mt < 4; mt++) {
                    ldsm_x4(al[0], al[1], al[2], al[3],
                            atL + (m_w + mt * 16 + a_row) * TROW + ks * 32 + a_kb);
#pragma unroll
                    for (int nt = 0; nt < 4; nt++)
                        mma16816(acc[mt][nt], al[0], al[1], al[2], al[3],
                                 bh[nt >> 1][(nt & 1) * 2], bh[nt >> 1][(nt & 1) * 2 + 1]);
                }
            }
        }
        __syncthreads();
    }

    const int g = lane >> 2;
    const int t2 = (lane & 3) * 2;
#pragma unroll
    for (int mt = 0; mt < 4; mt++) {
#pragma unroll
        for (int nt = 0; nt < 4; nt++) {
            int row = m0 + m_w + mt * 16 + g;
            int col = n0 + n_w + nt * 8 + t2;
            if (EPI == 0) {
                *(float2*)&C[(size_t)row * DD + col] = make_float2(acc[mt][nt][0], acc[mt][nt][1]);
                *(float2*)&C[(size_t)(row + 8) * DD + col] = make_float2(acc[mt][nt][2], acc[mt][nt][3]);
            } else {
                uint32_t hi, lo;
                split_pack2(acc[mt][nt][0], acc[mt][nt][1], hi, lo);
                *(uint32_t*)(Ch + (size_t)row * DD + col) = hi;
                *(uint32_t*)(Cl + (size_t)row * DD + col) = lo;
                split_pack2(acc[mt][nt][2], acc[mt][nt][3], hi, lo);
                *(uint32_t*)(Ch + (size_t)(row + 8) * DD + col) = hi;
                *(uint32_t*)(Cl + (size_t)(row + 8) * DD + col) = lo;
            }
        }
    }
}

// ---------------------------------------------------------------------------
// FA2-style flash attention on mma.sync, hi/lo bf16 3-pass for QK^T and PV.
// Each warp owns 16 full query rows: softmax is warp-local, and the S
// accumulator fragment is repacked into the P A-operand fragment entirely in
// registers (c0,c1->a0 / c2,c3->a1 / next n8 tile->a2,a3). One __syncthreads
// per 64-key tile (KV double-buffer rotation only).
// ---------------------------------------------------------------------------
#define AQROW 272
#define OFF_QH 0
#define OFF_QL 34816
#define OFF_KV 69632
#define KVSTAGE 69632            // Kh,Kl,Vh,Vl: 4 x 17408
#define ATTN_SMEM (OFF_KV + 2 * KVSTAGE)   // 208896
#define NT (SS / 64)             // 32

__device__ __forceinline__ void load_kv_stage(uint32_t sbase,
        const __nv_bfloat16* Kh, const __nv_bfloat16* Kl,
        const __nv_bfloat16* Vh, const __nv_bfloat16* Vl, size_t gbase, int tid) {
#pragma unroll
    for (int gr = tid; gr < 1024; gr += 256) {
        int r = gr >> 4;
        int c = (gr & 15) * 16;
        size_t go = gbase + (size_t)r * DD;
        cpa16(sbase +         r * AQROW + c, (const char*)(Kh + go) + c);
        cpa16(sbase + 17408 + r * AQROW + c, (const char*)(Kl + go) + c);
        cpa16(sbase + 34816 + r * AQROW + c, (const char*)(Vh + go) + c);
        cpa16(sbase + 52224 + r * AQROW + c, (const char*)(Vl + go) + c);
    }
}

__global__ __launch_bounds__(256, 1)
void attn_mma(const __nv_bfloat16* __restrict__ Qh_g, const __nv_bfloat16* __restrict__ Ql_g,
              const __nv_bfloat16* __restrict__ Kh_g, const __nv_bfloat16* __restrict__ Kl_g,
              const __nv_bfloat16* __restrict__ Vh_g, const __nv_bfloat16* __restrict__ Vl_g,
              __nv_bfloat16* __restrict__ Oh_g, __nv_bfloat16* __restrict__ Ol_g) {
    extern __shared__ char smem[];
    const uint32_t sb = smem_u32(smem);

    const int tid = threadIdx.x;
    const int wid = tid >> 5;
    const int lane = tid & 31;
    const int qt = blockIdx.x;           // 0..15
    const int bh = blockIdx.y;           // 0..31
    const int b  = bh >> 4;
    const int h  = bh & 15;

    const int m_w = wid * 16;            // warp owns rows [m_w, m_w+16)
    const int g   = lane >> 2;
    const int tc  = lane & 3;
    const int a_row = lane & 15;
    const int a_kb  = (lane >> 4) * 16;
    const int b_row = (lane & 7) + ((lane >> 4) << 3);
    const int b_kb  = ((lane >> 3) & 1) * 16;
    const int v_row = (lane & 7) + (((lane >> 3) & 1) << 3);
    const int v_cb  = (lane >> 4) * 16;

    const size_t qgbase = ((size_t)(b * SS + qt * 128)) * DD + (size_t)h * HD;
    const size_t kgbase = ((size_t)(b * SS)) * DD + (size_t)h * HD;

    // Q tile (128 x 128 hd), hi+lo
#pragma unroll
    for (int gr = tid; gr < 2048; gr += 256) {
        int r = gr >> 4;
        int c = (gr & 15) * 16;
        size_t go = qgbase + (size_t)r * DD;
        cpa16(sb + OFF_QH + r * AQROW + c, (const char*)(Qh_g + go) + c);
        cpa16(sb + OFF_QL + r * AQROW + c, (const char*)(Ql_g + go) + c);
    }
    load_kv_stage(sb + OFF_KV, Kh_g, Kl_g, Vh_g, Vl_g, kgbase, tid);
    cp_commit();   // group: {Q, KV stage 0}

    float o[16][4];
#pragma unroll
    for (int nt = 0; nt < 16; nt++)
#pragma unroll
        for (int c = 0; c < 4; c++) o[nt][c] = 0.f;
    float m0 = -1e30f, m1 = -1e30f, l0 = 0.f, l1 = 0.f;
    const float SCALE = 0.08838834764831845f;

    for (int kt = 0; kt < NT; kt++) {
        cp_wait<0>();
        __syncthreads();   // stage kt ready; all warps done reading stage kt+1's buffer

        if (kt < NT - 1) {
            load_kv_stage(sb + OFF_KV + ((kt + 1) & 1) * KVSTAGE,
                          Kh_g, Kl_g, Vh_g, Vl_g,
                          kgbase + (size_t)(kt + 1) * 64 * DD, tid);
            cp_commit();
        }

        const uint32_t kstH = sb + OFF_KV + (kt & 1) * KVSTAGE;
        const uint32_t kstL = kstH + 17408;
        const uint32_t vstH = kstH + 34816;
        const uint32_t vstL = kstH + 52224;

        // ---- S = (Qh+Ql)(Kh+Kl)^T, warp tile 16x64, 3 passes ----
        float s[8][4];
#pragma unroll
        for (int nt = 0; nt < 8; nt++)
#pragma unroll
            for (int c = 0; c < 4; c++) s[nt][c] = 0.f;

#pragma unroll
        for (int ks = 0; ks < 8; ks++) {
            uint32_t aq[4], bhf[4][4];
            ldsm_x4(aq[0], aq[1], aq[2], aq[3],
                    sb + OFF_QH + (m_w + a_row) * AQROW + ks * 32 + a_kb);
#pragma unroll
            for (int n16 = 0; n16 < 4; n16++)
                ldsm_x4(bhf[n16][0], bhf[n16][1], bhf[n16][2], bhf[n16][3],
                        kstH + (n16 * 16 + b_row) * AQROW + ks * 32 + b_kb);
            // Qh * Kh
#pragma unroll
            for (int nt = 0; nt < 8; nt++)
                mma16816(s[nt], aq[0], aq[1], aq[2], aq[3],
                         bhf[nt >> 1][(nt & 1) * 2], bhf[nt >> 1][(nt & 1) * 2 + 1]);
            // Ql * Kh
            {
                uint32_t al4[4];
                ldsm_x4(al4[0], al4[1], al4[2], al4[3],
                        sb + OFF_QL + (m_w + a_row) * AQROW + ks * 32 + a_kb);
#pragma unroll
                for (int nt = 0; nt < 8; nt++)
                    mma16816(s[nt], al4[0], al4[1], al4[2], al4[3],
                             bhf[nt >> 1][(nt & 1) * 2], bhf[nt >> 1][(nt & 1) * 2 + 1]);
            }
            // Qh * Kl
            {
                uint32_t blf[4];
#pragma unroll
                for (int n16 = 0; n16 < 4; n16++) {
                    ldsm_x4(blf[0], blf[1], blf[2], blf[3],
                            kstL + (n16 * 16 + b_row) * AQROW + ks * 32 + b_kb);
#pragma unroll
                    for (int half = 0; half < 2; half++)
                        mma16816(s[n16 * 2 + half], aq[0], aq[1], aq[2], aq[3],
                                 blf[half * 2], blf[half * 2 + 1]);
                }
            }
        }

        // ---- warp-local online softmax ----
        float mx0 = -1e30f, mx1 = -1e30f;
#pragma unroll
        for (int nt = 0; nt < 8; nt++) {
#pragma unroll
            for (int c = 0; c < 4; c++) s[nt][c] *= SCALE;
            mx0 = fmaxf(mx0, fmaxf(s[nt][0], s[nt][1]));
            mx1 = fmaxf(mx1, fmaxf(s[nt][2], s[nt][3]));
        }
        mx0 = fmaxf(mx0, __shfl_xor_sync(0xffffffffu, mx0, 1));
        mx0 = fmaxf(mx0, __shfl_xor_sync(0xffffffffu, mx0, 2));
        mx1 = fmaxf(mx1, __shfl_xor_sync(0xffffffffu, mx1, 1));
        mx1 = fmaxf(mx1, __shfl_xor_sync(0xffffffffu, mx1, 2));
        float mn0 = fmaxf(m0, mx0), mn1 = fmaxf(m1, mx1);
        float sc0 = __expf(m0 - mn0), sc1 = __expf(m1 - mn1);
        m0 = mn0; m1 = mn1;

        float sum0 = 0.f, sum1 = 0.f;
#pragma unroll
        for (int nt = 0; nt < 8; nt++) {
            s[nt][0] = __expf(s[nt][0] - mn0);
            s[nt][1] = __expf(s[nt][1] - mn0);
            s[nt][2] = __expf(s[nt][2] - mn1);
            s[nt][3] = __expf(s[nt][3] - mn1);
            sum0 += s[nt][0] + s[nt][1];
            sum1 += s[nt][2] + s[nt][3];
        }
        sum0 += __shfl_xor_sync(0xffffffffu, sum0, 1);
        sum0 += __shfl_xor_sync(0xffffffffu, sum0, 2);
        sum1 += __shfl_xor_sync(0xffffffffu, sum1, 1);
        sum1 += __shfl_xor_sync(0xffffffffu, sum1, 2);
        l0 = l0 * sc0 + sum0;
        l1 = l1 * sc1 + sum1;
#pragma unroll
        for (int nt = 0; nt < 16; nt++) {
            o[nt][0] *= sc0; o[nt][1] *= sc0;
            o[nt][2] *= sc1; o[nt][3] *= sc1;
        }

        // ---- O += (Ph+Pl)(Vh+Vl), P from registers, warp tile 16x128 ----
#pragma unroll
        for (int ks = 0; ks < 4; ks++) {
            uint32_t aph[4], apl[4];
            split_pack2(s[2 * ks][0],     s[2 * ks][1],     aph[0], apl[0]);
            split_pack2(s[2 * ks][2],     s[2 * ks][3],     aph[1], apl[1]);
            split_pack2(s[2 * ks + 1][0], s[2 * ks + 1][1], aph[2], apl[2]);
            split_pack2(s[2 * ks + 1][2], s[2 * ks + 1][3], aph[3], apl[3]);
#pragma unroll
            for (int cg = 0; cg < 8; cg++) {
                uint32_t vh4[4];
                ldsm_x4_trans(vh4[0], vh4[1], vh4[2], vh4[3],
                              vstH + (ks * 16 + v_row) * AQROW + cg * 32 + v_cb);
                mma16816(o[2 * cg],     aph[0], aph[1], aph[2], aph[3], vh4[0], vh4[1]);
                mma16816(o[2 * cg + 1], aph[0], aph[1], aph[2], aph[3], vh4[2], vh4[3]);
                mma16816(o[2 * cg],     apl[0], apl[1], apl[2], apl[3], vh4[0], vh4[1]);
                mma16816(o[2 * cg + 1], apl[0], apl[1], apl[2], apl[3], vh4[2], vh4[3]);
                uint32_t vl4[4];
                ldsm_x4_trans(vl4[0], vl4[1], vl4[2], vl4[3],
                              vstL + (ks * 16 + v_row) * AQROW + cg * 32 + v_cb);
                mma16816(o[2 * cg],     aph[0], aph[1], aph[2], aph[3], vl4[0], vl4[1]);
                mma16816(o[2 * cg + 1], aph[0], aph[1], aph[2], aph[3], vl4[2], vl4[3]);
            }
        }
    }

    // ---- epilogue: normalize, split hi/lo, store ----
    const float inv0 = 1.0f / l0;
    const float inv1 = 1.0f / l1;
    const size_t row0 = (size_t)(b * SS + qt * 128 + m_w + g);
    const size_t row1 = row0 + 8;
#pragma unroll
    for (int nt = 0; nt < 16; nt++) {
        int col = h * HD + nt * 8 + 2 * tc;
        uint32_t hi, lo;
        split_pack2(o[nt][0] * inv0, o[nt][1] * inv0, hi, lo);
        *(uint32_t*)(Oh_g + row0 * DD + col) = hi;
        *(uint32_t*)(Ol_g + row0 * DD + col) = lo;
        split_pack2(o[nt][2] * inv1, o[nt][3] * inv1, hi, lo);
        *(uint32_t*)(Oh_g + row1 * DD + col) = hi;
        *(uint32_t*)(Ol_g + row1 * DD + col) = lo;
    }
}

// ---------------------------------------------------------------------------
extern "C" void kernel_launch(void* const* d_in, const int* in_sizes, int n_in,
                              void* d_out, int out_size) {
    const float* x  = (const float*)d_in[0];
    const float* wq = (const float*)d_in[1];
    const float* wk = (const float*)d_in[2];
    const float* wv = (const float*)d_in[3];
    const float* wo = (const float*)d_in[4];
    float* out = (float*)d_out;

    __nv_bfloat16 *xh, *xl, *qh, *ql, *kh, *kl, *vh, *vl, *ah, *al, *wh, *wl;
    cudaGetSymbolAddress((void**)&xh, g_xh);
    cudaGetSymbolAddress((void**)&xl, g_xl);
    cudaGetSymbolAddress((void**)&qh, g_qh);
    cudaGetSymbolAddress((void**)&ql, g_ql);
    cudaGetSymbolAddress((void**)&kh, g_kh);
    cudaGetSymbolAddress((void**)&kl, g_kl);
    cudaGetSymbolAddress((void**)&vh, g_vh);
    cudaGetSymbolAddress((void**)&vl, g_vl);
    cudaGetSymbolAddress((void**)&ah, g_ah);
    cudaGetSymbolAddress((void**)&al, g_al);
    cudaGetSymbolAddress((void**)&wh, g_wh);
    cudaGetSymbolAddress((void**)&wl, g_wl);

    cudaFuncSetAttribute(gemm_mma<0>, cudaFuncAttributeMaxDynamicSharedMemorySize, GEMM_SMEM);
    cudaFuncSetAttribute(gemm_mma<1>, cudaFuncAttributeMaxDynamicSharedMemorySize, GEMM_SMEM);
    cudaFuncSetAttribute(attn_mma, cudaFuncAttributeMaxDynamicSharedMemorySize, ATTN_SMEM);

    const size_t WN = (size_t)DD * DD;
    const int n4x = (MROWS * DD) / 4;
    const int n4w = (DD * DD) / 4;

    cvt_hilo<<<(n4x + 255) / 256, 256>>>((const float4*)x, (uint2*)xh, (uint2*)xl, n4x);
    cvt_hilo<<<(n4w + 255) / 256, 256>>>((const float4*)wq, (uint2*)(wh + 0 * WN), (uint2*)(wl + 0 * WN), n4w);
    cvt_hilo<<<(n4w + 255) / 256, 256>>>((const float4*)wk, (uint2*)(wh + 1 * WN), (uint2*)(wl + 1 * WN), n4w);
    cvt_hilo<<<(n4w + 255) / 256, 256>>>((const float4*)wv, (uint2*)(wh + 2 * WN), (uint2*)(wl + 2 * WN), n4w);
    cvt_hilo<<<(n4w + 255) / 256, 256>>>((const float4*)wo, (uint2*)(wh + 3 * WN), (uint2*)(wl + 3 * WN), n4w);

    dim3 ggrid(DD / 128, MROWS / 128);  // (16, 32)
    gemm_mma<1><<<ggrid, 256, GEMM_SMEM>>>(xh, xl, wh + 0 * WN, wl + 0 * WN, nullptr, qh, ql);
    gemm_mma<1><<<ggrid, 256, GEMM_SMEM>>>(xh, xl, wh + 1 * WN, wl + 1 * WN, nullptr, kh, kl);
    gemm_mma<1><<<ggrid, 256, GEMM_SMEM>>>(xh, xl, wh + 2 * WN, wl + 2 * WN, nullptr, vh, vl);

    attn_mma<<<dim3(16, 32), 256, ATTN_SMEM>>>(qh, ql, kh, kl, vh, vl, ah, al);

    gemm_mma<0><<<ggrid, 256, GEMM_SMEM>>>(ah, al, wh + 3 * WN, wl + 3 * WN, out, nullptr, nullptr);
}

// round 8
// speedup vs baseline: 3.4441x; 1.0010x over previous
#include <cuda_runtime.h>
#include <cuda_bf16.h>
#include <math.h>
#include <stdint.h>

// Problem constants
#define BB 2
#define SS 2048
#define DD 2048
#define HH 16
#define HD 128
#define MROWS (BB*SS)   // 4096
#define GK DD           // 2048

// ---------------------------------------------------------------------------
// Scratch (allocation-free rule: __device__ globals)
// ---------------------------------------------------------------------------
__device__ __nv_bfloat16 g_xh[(size_t)MROWS*DD];
__device__ __nv_bfloat16 g_xl[(size_t)MROWS*DD];
__device__ __nv_bfloat16 g_qh[(size_t)MROWS*DD];
__device__ __nv_bfloat16 g_ql[(size_t)MROWS*DD];
__device__ __nv_bfloat16 g_kh[(size_t)MROWS*DD];
__device__ __nv_bfloat16 g_kl[(size_t)MROWS*DD];
__device__ __nv_bfloat16 g_vh[(size_t)MROWS*DD];
__device__ __nv_bfloat16 g_vl[(size_t)MROWS*DD];
__device__ __nv_bfloat16 g_ah[(size_t)MROWS*DD];
__device__ __nv_bfloat16 g_al[(size_t)MROWS*DD];
__device__ __nv_bfloat16 g_wh[(size_t)4*DD*DD];
__device__ __nv_bfloat16 g_wl[(size_t)4*DD*DD];

// ---------------------------------------------------------------------------
// PTX helpers (sm_100 BASELINE only)
// ---------------------------------------------------------------------------
__device__ __forceinline__ uint32_t smem_u32(const void* p) {
    uint32_t a;
    asm("{ .reg .u64 t; cvta.to.shared.u64 t, %1; cvt.u32.u64 %0, t; }" : "=r"(a) : "l"(p));
    return a;
}
__device__ __forceinline__ void cpa16(uint32_t dst, const void* src) {
    asm volatile("cp.async.cg.shared.global [%0], [%1], 16;\n" :: "r"(dst), "l"(src));
}
__device__ __forceinline__ void cp_commit() {
    asm volatile("cp.async.commit_group;" ::: "memory");
}
template <int N>
__device__ __forceinline__ void cp_wait() {
    asm volatile("cp.async.wait_group %0;" :: "n"(N) : "memory");
}
__device__ __forceinline__ void ldsm_x4(uint32_t& r0, uint32_t& r1, uint32_t& r2, uint32_t& r3,
                                        uint32_t addr) {
    asm volatile("ldmatrix.sync.aligned.m8n8.x4.shared.b16 {%0,%1,%2,%3}, [%4];"
                 : "=r"(r0), "=r"(r1), "=r"(r2), "=r"(r3) : "r"(addr));
}
__device__ __forceinline__ void ldsm_x4_trans(uint32_t& r0, uint32_t& r1, uint32_t& r2, uint32_t& r3,
                                              uint32_t addr) {
    asm volatile("ldmatrix.sync.aligned.m8n8.x4.trans.shared.b16 {%0,%1,%2,%3}, [%4];"
                 : "=r"(r0), "=r"(r1), "=r"(r2), "=r"(r3) : "r"(addr));
}
__device__ __forceinline__ void mma16816(float* c, uint32_t a0, uint32_t a1, uint32_t a2,
                                         uint32_t a3, uint32_t b0, uint32_t b1) {
    asm volatile(
        "mma.sync.aligned.m16n8k16.row.col.f32.bf16.bf16.f32 "
        "{%0,%1,%2,%3}, {%4,%5,%6,%7}, {%8,%9}, {%0,%1,%2,%3};"
        : "+f"(c[0]), "+f"(c[1]), "+f"(c[2]), "+f"(c[3])
        : "r"(a0), "r"(a1), "r"(a2), "r"(a3), "r"(b0), "r"(b1));
}
// split (a,b) fp32 into packed bf16 hi pair + lo (residual) pair
__device__ __forceinline__ void split_pack2(float a, float b, uint32_t& hi, uint32_t& lo) {
    __nv_bfloat16 ha = __float2bfloat16_rn(a);
    __nv_bfloat16 hb = __float2bfloat16_rn(b);
    float ra = a - __bfloat162float(ha);
    float rb = b - __bfloat162float(hb);
    hi = (uint32_t)__bfloat16_as_ushort(ha) | ((uint32_t)__bfloat16_as_ushort(hb) << 16);
    lo = (uint32_t)__bfloat16_as_ushort(__float2bfloat16_rn(ra)) |
         ((uint32_t)__bfloat16_as_ushort(__float2bfloat16_rn(rb)) << 16);
}

// ---------------------------------------------------------------------------
// fp32 -> bf16 hi/lo conversion
// ---------------------------------------------------------------------------
__global__ void cvt_hilo(const float4* __restrict__ src, uint2* __restrict__ hi,
                         uint2* __restrict__ lo, int n4) {
    int i = blockIdx.x * blockDim.x + threadIdx.x;
    if (i >= n4) return;
    float4 v = src[i];
    uint2 uh, ul;
    split_pack2(v.x, v.y, uh.x, ul.x);
    split_pack2(v.z, v.w, uh.y, ul.y);
    hi[i] = uh;
    lo[i] = ul;
}

// ---------------------------------------------------------------------------
// mma.sync GEMM: C = (Ah+Al)*(Bh+Bl)^T, dropping Al*Bl.
// 128x128 CTA tile, K-chunk 32, double-buffered cp.async, 8 warps (2Mx4N).
// ks-outer mainloop: A-hi and B-hi fragments reused across the 3 passes.
// ---------------------------------------------------------------------------
#define TROW 80
#define TILE_BYTES (128 * TROW)
#define STAGE_BYTES (4 * TILE_BYTES)
#define GEMM_SMEM (2 * STAGE_BYTES)   // 81920
#define NCHUNK (GK / 32)

__device__ __forceinline__ void load_stage(uint32_t sbase,
        const __nv_bfloat16* Ah, const __nv_bfloat16* Al,
        const __nv_bfloat16* Bh, const __nv_bfloat16* Bl,
        int m0, int n0, int kc, int tid) {
    const size_t k0 = (size_t)kc * 32;
    const char* bases[4] = {
        (const char*)(Ah + (size_t)m0 * GK + k0),
        (const char*)(Al + (size_t)m0 * GK + k0),
        (const char*)(Bh + (size_t)n0 * GK + k0),
        (const char*)(Bl + (size_t)n0 * GK + k0) };
#pragma unroll
    for (int tile = 0; tile < 4; tile++) {
        const char* bp = bases[tile];
        const uint32_t tb = sbase + tile * TILE_BYTES;
#pragma unroll
        for (int t = 0; t < 2; t++) {
            int g = tid + t * 256;
            int r = g >> 2;
            int c = (g & 3) * 16;
            cpa16(tb + r * TROW + c, bp + (size_t)r * (GK * 2) + c);
        }
    }
}

template<int EPI>
__global__ __launch_bounds__(256, 2)
void gemm_mma(const __nv_bfloat16* __restrict__ Ah, const __nv_bfloat16* __restrict__ Al,
              const __nv_bfloat16* __restrict__ Bh, const __nv_bfloat16* __restrict__ Bl,
              float* __restrict__ C,
              __nv_bfloat16* __restrict__ Ch, __nv_bfloat16* __restrict__ Cl) {
    extern __shared__ char smem[];
    const uint32_t sb = smem_u32(smem);
    const int tid = threadIdx.x;
    const int wid = tid >> 5;
    const int lane = tid & 31;
    const int m0 = blockIdx.y * 128;
    const int n0 = blockIdx.x * 128;
    const int m_w = (wid & 1) * 64;
    const int n_w = (wid >> 1) * 32;

    float acc[4][4][4];
#pragma unroll
    for (int i = 0; i < 4; i++)
#pragma unroll
        for (int j = 0; j < 4; j++)
#pragma unroll
            for (int r = 0; r < 4; r++) acc[i][j][r] = 0.f;

    const int a_row = lane & 15;
    const int a_kb  = (lane >> 4) * 16;
    const int b_row = (lane & 7) + ((lane >> 4) << 3);
    const int b_kb  = ((lane >> 3) & 1) * 16;

    load_stage(sb, Ah, Al, Bh, Bl, m0, n0, 0, tid);
    cp_commit();

    for (int kc = 0; kc < NCHUNK; kc++) {
        if (kc < NCHUNK - 1) {
            load_stage(sb + ((kc + 1) & 1) * STAGE_BYTES, Ah, Al, Bh, Bl, m0, n0, kc + 1, tid);
            cp_commit();
            cp_wait<1>();
        } else {
            cp_wait<0>();
        }
        __syncthreads();

        const uint32_t stage = sb + (kc & 1) * STAGE_BYTES;
        const uint32_t atH = stage;
        const uint32_t atL = stage + TILE_BYTES;
        const uint32_t btH = stage + 2 * TILE_BYTES;
        const uint32_t btL = stage + 3 * TILE_BYTES;
#pragma unroll
        for (int ks = 0; ks < 2; ks++) {
            uint32_t aq[4][4], bh[2][4];
#pragma unroll
            for (int mt = 0; mt < 4; mt++)
                ldsm_x4(aq[mt][0], aq[mt][1], aq[mt][2], aq[mt][3],
                        atH + (m_w + mt * 16 + a_row) * TROW + ks * 32 + a_kb);
#pragma unroll
            for (int bq = 0; bq < 2; bq++)
                ldsm_x4(bh[bq][0], bh[bq][1], bh[bq][2], bh[bq][3],
                        btH + (n_w + bq * 16 + b_row) * TROW + ks * 32 + b_kb);
            // Ah * Bh
#pragma unroll
            for (int mt = 0; mt < 4; mt++)
#pragma unroll
                for (int nt = 0; nt < 4; nt++)
                    mma16816(acc[mt][nt], aq[mt][0], aq[mt][1], aq[mt][2], aq[mt][3],
                             bh[nt >> 1][(nt & 1) * 2], bh[nt >> 1][(nt & 1) * 2 + 1]);
            // Ah * Bl
            {
                uint32_t bl[2][4];
#pragma unroll
                for (int bq = 0; bq < 2; bq++)
                    ldsm_x4(bl[bq][0], bl[bq][1], bl[bq][2], bl[bq][3],
                            btL + (n_w + bq * 16 + b_row) * TROW + ks * 32 + b_kb);
#pragma unroll
                for (int mt = 0; mt < 4; mt++)
#pragma unroll
                    for (int nt = 0; nt < 4; nt++)
                        mma16816(acc[mt][nt], aq[mt][0], aq[mt][1], aq[mt][2], aq[mt][3],
                                 bl[nt >> 1][(nt & 1) * 2], bl[nt >> 1][(nt & 1) * 2 + 1]);
            }
            // Al * Bh
            {
                uint32_t al[4];
#pragma unroll
                for (int mt = 0; mt < 4; mt++) {
                    ldsm_x4(al[0], al[1], al[2], al[3],
                            atL + (m_w + mt * 16 + a_row) * TROW + ks * 32 + a_kb);
#pragma unroll
                    for (int nt = 0; nt < 4; nt++)
                        mma16816(acc[mt][nt], al[0], al[1], al[2], al[3],
                                 bh[nt >> 1][(nt & 1) * 2], bh[nt >> 1][(nt & 1) * 2 + 1]);
                }
            }
        }
        __syncthreads();
    }

    const int g = lane >> 2;
    const int t2 = (lane & 3) * 2;
#pragma unroll
    for (int mt = 0; mt < 4; mt++) {
#pragma unroll
        for (int nt = 0; nt < 4; nt++) {
            int row = m0 + m_w + mt * 16 + g;
            int col = n0 + n_w + nt * 8 + t2;
            if (EPI == 0) {
                *(float2*)&C[(size_t)row * DD + col] = make_float2(acc[mt][nt][0], acc[mt][nt][1]);
                *(float2*)&C[(size_t)(row + 8) * DD + col] = make_float2(acc[mt][nt][2], acc[mt][nt][3]);
            } else {
                uint32_t hi, lo;
                split_pack2(acc[mt][nt][0], acc[mt][nt][1], hi, lo);
                *(uint32_t*)(Ch + (size_t)row * DD + col) = hi;
                *(uint32_t*)(Cl + (size_t)row * DD + col) = lo;
                split_pack2(acc[mt][nt][2], acc[mt][nt][3], hi, lo);
                *(uint32_t*)(Ch + (size_t)(row + 8) * DD + col) = hi;
                *(uint32_t*)(Cl + (size_t)(row + 8) * DD + col) = lo;
            }
        }
    }
}

// ---------------------------------------------------------------------------
// FA2-style flash attention on mma.sync, hi/lo bf16 3-pass for QK^T and PV.
// Each warp owns 16 full query rows: softmax is warp-local, and the S
// accumulator fragment is repacked into the P A-operand fragment entirely in
// registers (c0,c1->a0 / c2,c3->a1 / next n8 tile->a2,a3). One __syncthreads
// per 64-key tile (KV double-buffer rotation only).
// ---------------------------------------------------------------------------
#define AQROW 272
#define OFF_QH 0
#define OFF_QL 34816
#define OFF_KV 69632
#define KVSTAGE 69632            // Kh,Kl,Vh,Vl: 4 x 17408
#define ATTN_SMEM (OFF_KV + 2 * KVSTAGE)   // 208896
#define NT (SS / 64)             // 32

__device__ __forceinline__ void load_kv_stage(uint32_t sbase,
        const __nv_bfloat16* Kh, const __nv_bfloat16* Kl,
        const __nv_bfloat16* Vh, const __nv_bfloat16* Vl, size_t gbase, int tid) {
#pragma unroll
    for (int gr = tid; gr < 1024; gr += 256) {
        int r = gr >> 4;
        int c = (gr & 15) * 16;
        size_t go = gbase + (size_t)r * DD;
        cpa16(sbase +         r * AQROW + c, (const char*)(Kh + go) + c);
        cpa16(sbase + 17408 + r * AQROW + c, (const char*)(Kl + go) + c);
        cpa16(sbase + 34816 + r * AQROW + c, (const char*)(Vh + go) + c);
        cpa16(sbase + 52224 + r * AQROW + c, (const char*)(Vl + go) + c);
    }
}

__global__ __launch_bounds__(256, 1)
void attn_mma(const __nv_bfloat16* __restrict__ Qh_g, const __nv_bfloat16* __restrict__ Ql_g,
              const __nv_bfloat16* __restrict__ Kh_g, const __nv_bfloat16* __restrict__ Kl_g,
              const __nv_bfloat16* __restrict__ Vh_g, const __nv_bfloat16* __restrict__ Vl_g,
              __nv_bfloat16* __restrict__ Oh_g, __nv_bfloat16* __restrict__ Ol_g) {
    extern __shared__ char smem[];
    const uint32_t sb = smem_u32(smem);

    const int tid = threadIdx.x;
    const int wid = tid >> 5;
    const int lane = tid & 31;
    const int qt = blockIdx.x;           // 0..15
    const int bh = blockIdx.y;           // 0..31
    const int b  = bh >> 4;
    const int h  = bh & 15;

    const int m_w = wid * 16;            // warp owns rows [m_w, m_w+16)
    const int g   = lane >> 2;
    const int tc  = lane & 3;
    const int a_row = lane & 15;
    const int a_kb  = (lane >> 4) * 16;
    const int b_row = (lane & 7) + ((lane >> 4) << 3);
    const int b_kb  = ((lane >> 3) & 1) * 16;
    const int v_row = (lane & 7) + (((lane >> 3) & 1) << 3);
    const int v_cb  = (lane >> 4) * 16;

    const size_t qgbase = ((size_t)(b * SS + qt * 128)) * DD + (size_t)h * HD;
    const size_t kgbase = ((size_t)(b * SS)) * DD + (size_t)h * HD;

    // Q tile (128 x 128 hd), hi+lo
#pragma unroll
    for (int gr = tid; gr < 2048; gr += 256) {
        int r = gr >> 4;
        int c = (gr & 15) * 16;
        size_t go = qgbase + (size_t)r * DD;
        cpa16(sb + OFF_QH + r * AQROW + c, (const char*)(Qh_g + go) + c);
        cpa16(sb + OFF_QL + r * AQROW + c, (const char*)(Ql_g + go) + c);
    }
    load_kv_stage(sb + OFF_KV, Kh_g, Kl_g, Vh_g, Vl_g, kgbase, tid);
    cp_commit();   // group: {Q, KV stage 0}

    float o[16][4];
#pragma unroll
    for (int nt = 0; nt < 16; nt++)
#pragma unroll
        for (int c = 0; c < 4; c++) o[nt][c] = 0.f;
    float m0 = -1e30f, m1 = -1e30f, l0 = 0.f, l1 = 0.f;
    const float SCALE = 0.08838834764831845f;

    for (int kt = 0; kt < NT; kt++) {
        cp_wait<0>();
        __syncthreads();   // stage kt ready; all warps done reading stage kt+1's buffer

        if (kt < NT - 1) {
            load_kv_stage(sb + OFF_KV + ((kt + 1) & 1) * KVSTAGE,
                          Kh_g, Kl_g, Vh_g, Vl_g,
                          kgbase + (size_t)(kt + 1) * 64 * DD, tid);
            cp_commit();
        }

        const uint32_t kstH = sb + OFF_KV + (kt & 1) * KVSTAGE;
        const uint32_t kstL = kstH + 17408;
        const uint32_t vstH = kstH + 34816;
        const uint32_t vstL = kstH + 52224;

        // ---- S = (Qh+Ql)(Kh+Kl)^T, warp tile 16x64, 3 passes ----
        float s[8][4];
#pragma unroll
        for (int nt = 0; nt < 8; nt++)
#pragma unroll
            for (int c = 0; c < 4; c++) s[nt][c] = 0.f;

#pragma unroll
        for (int ks = 0; ks < 8; ks++) {
            uint32_t aq[4], bhf[4][4];
            ldsm_x4(aq[0], aq[1], aq[2], aq[3],
                    sb + OFF_QH + (m_w + a_row) * AQROW + ks * 32 + a_kb);
#pragma unroll
            for (int n16 = 0; n16 < 4; n16++)
                ldsm_x4(bhf[n16][0], bhf[n16][1], bhf[n16][2], bhf[n16][3],
                        kstH + (n16 * 16 + b_row) * AQROW + ks * 32 + b_kb);
            // Qh * Kh
#pragma unroll
            for (int nt = 0; nt < 8; nt++)
                mma16816(s[nt], aq[0], aq[1], aq[2], aq[3],
                         bhf[nt >> 1][(nt & 1) * 2], bhf[nt >> 1][(nt & 1) * 2 + 1]);
            // Ql * Kh
            {
                uint32_t al4[4];
                ldsm_x4(al4[0], al4[1], al4[2], al4[3],
                        sb + OFF_QL + (m_w + a_row) * AQROW + ks * 32 + a_kb);
#pragma unroll
                for (int nt = 0; nt < 8; nt++)
                    mma16816(s[nt], al4[0], al4[1], al4[2], al4[3],
                             bhf[nt >> 1][(nt & 1) * 2], bhf[nt >> 1][(nt & 1) * 2 + 1]);
            }
            // Qh * Kl
            {
                uint32_t blf[4];
#pragma unroll
                for (int n16 = 0; n16 < 4; n16++) {
                    ldsm_x4(blf[0], blf[1], blf[2], blf[3],
                            kstL + (n16 * 16 + b_row) * AQROW + ks * 32 + b_kb);
#pragma unroll
                    for (int half = 0; half < 2; half++)
                        mma16816(s[n16 * 2 + half], aq[0], aq[1], aq[2], aq[3],
                                 blf[half * 2], blf[half * 2 + 1]);
                }
            }
        }

        // ---- warp-local online softmax ----
        float mx0 = -1e30f, mx1 = -1e30f;
#pragma unroll
        for (int nt = 0; nt < 8; nt++) {
#pragma unroll
            for (int c = 0; c < 4; c++) s[nt][c] *= SCALE;
            mx0 = fmaxf(mx0, fmaxf(s[nt][0], s[nt][1]));
            mx1 = fmaxf(mx1, fmaxf(s[nt][2], s[nt][3]));
        }
        mx0 = fmaxf(mx0, __shfl_xor_sync(0xffffffffu, mx0, 1));
        mx0 = fmaxf(mx0, __shfl_xor_sync(0xffffffffu, mx0, 2));
        mx1 = fmaxf(mx1, __shfl_xor_sync(0xffffffffu, mx1, 1));
        mx1 = fmaxf(mx1, __shfl_xor_sync(0xffffffffu, mx1, 2));
        float mn0 = fmaxf(m0, mx0), mn1 = fmaxf(m1, mx1);
        float sc0 = __expf(m0 - mn0), sc1 = __expf(m1 - mn1);
        m0 = mn0; m1 = mn1;

        float sum0 = 0.f, sum1 = 0.f;
#pragma unroll
        for (int nt = 0; nt < 8; nt++) {
            s[nt][0] = __expf(s[nt][0] - mn0);
            s[nt][1] = __expf(s[nt][1] - mn0);
            s[nt][2] = __expf(s[nt][2] - mn1);
            s[nt][3] = __expf(s[nt][3] - mn1);
            sum0 += s[nt][0] + s[nt][1];
            sum1 += s[nt][2] + s[nt][3];
        }
        sum0 += __shfl_xor_sync(0xffffffffu, sum0, 1);
        sum0 += __shfl_xor_sync(0xffffffffu, sum0, 2);
        sum1 += __shfl_xor_sync(0xffffffffu, sum1, 1);
        sum1 += __shfl_xor_sync(0xffffffffu, sum1, 2);
        l0 = l0 * sc0 + sum0;
        l1 = l1 * sc1 + sum1;
#pragma unroll
        for (int nt = 0; nt < 16; nt++) {
            o[nt][0] *= sc0; o[nt][1] *= sc0;
            o[nt][2] *= sc1; o[nt][3] *= sc1;
        }

        // ---- O += (Ph+Pl)(Vh+Vl), P from registers, warp tile 16x128 ----
#pragma unroll
        for (int ks = 0; ks < 4; ks++) {
            uint32_t aph[4], apl[4];
            split_pack2(s[2 * ks][0],     s[2 * ks][1],     aph[0], apl[0]);
            split_pack2(s[2 * ks][2],     s[2 * ks][3],     aph[1], apl[1]);
            split_pack2(s[2 * ks + 1][0], s[2 * ks + 1][1], aph[2], apl[2]);
            split_pack2(s[2 * ks + 1][2], s[2 * ks + 1][3], aph[3], apl[3]);
#pragma unroll
            for (int cg = 0; cg < 8; cg++) {
                uint32_t vh4[4];
                ldsm_x4_trans(vh4[0], vh4[1], vh4[2], vh4[3],
                              vstH + (ks * 16 + v_row) * AQROW + cg * 32 + v_cb);
                mma16816(o[2 * cg],     aph[0], aph[1], aph[2], aph[3], vh4[0], vh4[1]);
                mma16816(o[2 * cg + 1], aph[0], aph[1], aph[2], aph[3], vh4[2], vh4[3]);
                mma16816(o[2 * cg],     apl[0], apl[1], apl[2], apl[3], vh4[0], vh4[1]);
                mma16816(o[2 * cg + 1], apl[0], apl[1], apl[2], apl[3], vh4[2], vh4[3]);
                uint32_t vl4[4];
                ldsm_x4_trans(vl4[0], vl4[1], vl4[2], vl4[3],
                              vstL + (ks * 16 + v_row) * AQROW + cg * 32 + v_cb);
                mma16816(o[2 * cg],     aph[0], aph[1], aph[2], aph[3], vl4[0], vl4[1]);
                mma16816(o[2 * cg + 1], aph[0], aph[1], aph[2], aph[3], vl4[2], vl4[3]);
            }
        }
    }

    // ---- epilogue: normalize, split hi/lo, store ----
    const float inv0 = 1.0f / l0;
    const float inv1 = 1.0f / l1;
    const size_t row0 = (size_t)(b * SS + qt * 128 + m_w + g);
    const size_t row1 = row0 + 8;
#pragma unroll
    for (int nt = 0; nt < 16; nt++) {
        int col = h * HD + nt * 8 + 2 * tc;
        uint32_t hi, lo;
        split_pack2(o[nt][0] * inv0, o[nt][1] * inv0, hi, lo);
        *(uint32_t*)(Oh_g + row0 * DD + col) = hi;
        *(uint32_t*)(Ol_g + row0 * DD + col) = lo;
        split_pack2(o[nt][2] * inv1, o[nt][3] * inv1, hi, lo);
        *(uint32_t*)(Oh_g + row1 * DD + col) = hi;
        *(uint32_t*)(Ol_g + row1 * DD + col) = lo;
    }
}

// ---------------------------------------------------------------------------
extern "C" void kernel_launch(void* const* d_in, const int* in_sizes, int n_in,
                              void* d_out, int out_size) {
    const float* x  = (const float*)d_in[0];
    const float* wq = (const float*)d_in[1];
    const float* wk = (const float*)d_in[2];
    const float* wv = (const float*)d_in[3];
    const float* wo = (const float*)d_in[4];
    float* out = (float*)d_out;

    __nv_bfloat16 *xh, *xl, *qh, *ql, *kh, *kl, *vh, *vl, *ah, *al, *wh, *wl;
    cudaGetSymbolAddress((void**)&xh, g_xh);
    cudaGetSymbolAddress((void**)&xl, g_xl);
    cudaGetSymbolAddress((void**)&qh, g_qh);
    cudaGetSymbolAddress((void**)&ql, g_ql);
    cudaGetSymbolAddress((void**)&kh, g_kh);
    cudaGetSymbolAddress((void**)&kl, g_kl);
    cudaGetSymbolAddress((void**)&vh, g_vh);
    cudaGetSymbolAddress((void**)&vl, g_vl);
    cudaGetSymbolAddress((void**)&ah, g_ah);
    cudaGetSymbolAddress((void**)&al, g_al);
    cudaGetSymbolAddress((void**)&wh, g_wh);
    cudaGetSymbolAddress((void**)&wl, g_wl);

    cudaFuncSetAttribute(gemm_mma<0>, cudaFuncAttributeMaxDynamicSharedMemorySize, GEMM_SMEM);
    cudaFuncSetAttribute(gemm_mma<1>, cudaFuncAttributeMaxDynamicSharedMemorySize, GEMM_SMEM);
    cudaFuncSetAttribute(attn_mma, cudaFuncAttributeMaxDynamicSharedMemorySize, ATTN_SMEM);

    const size_t WN = (size_t)DD * DD;
    const int n4x = (MROWS * DD) / 4;
    const int n4w = (DD * DD) / 4;

    cvt_hilo<<<(n4x + 255) / 256, 256>>>((const float4*)x, (uint2*)xh, (uint2*)xl, n4x);
    cvt_hilo<<<(n4w + 255) / 256, 256>>>((const float4*)wq, (uint2*)(wh + 0 * WN), (uint2*)(wl + 0 * WN), n4w);
    cvt_hilo<<<(n4w + 255) / 256, 256>>>((const float4*)wk, (uint2*)(wh + 1 * WN), (uint2*)(wl + 1 * WN), n4w);
    cvt_hilo<<<(n4w + 255) / 256, 256>>>((const float4*)wv, (uint2*)(wh + 2 * WN), (uint2*)(wl + 2 * WN), n4w);
    cvt_hilo<<<(n4w + 255) / 256, 256>>>((const float4*)wo, (uint2*)(wh + 3 * WN), (uint2*)(wl + 3 * WN), n4w);

    dim3 ggrid(DD / 128, MROWS / 128);  // (16, 32)
    gemm_mma<1><<<ggrid, 256, GEMM_SMEM>>>(xh, xl, wh + 0 * WN, wl + 0 * WN, nullptr, qh, ql);
    gemm_mma<1><<<ggrid, 256, GEMM_SMEM>>>(xh, xl, wh + 1 * WN, wl + 1 * WN, nullptr, kh, kl);
    gemm_mma<1><<<ggrid, 256, GEMM_SMEM>>>(xh, xl, wh + 2 * WN, wl + 2 * WN, nullptr, vh, vl);

    attn_mma<<<dim3(16, 32), 256, ATTN_SMEM>>>(qh, ql, kh, kl, vh, vl, ah, al);

    gemm_mma<0><<<ggrid, 256, GEMM_SMEM>>>(ah, al, wh + 3 * WN, wl + 3 * WN, out, nullptr, nullptr);
}